// round 1
// baseline (speedup 1.0000x reference)
#include <cuda_runtime.h>
#include <math.h>

// Problem constants
#define T_   8
#define N_   20000
#define C_   128
#define E_   320000
#define H_   4
#define DH_  32
#define WIN_ 4
#define K_   5
#define CH_  512
#define TN_  (T_ * N_)

// ---------------------------------------------------------------------------
// Scratch (no cudaMalloc allowed -> __device__ globals)
// ---------------------------------------------------------------------------
__device__ float g_deg[N_];
__device__ float g_inv[N_];
__device__ float g_B1[T_ * N_ * C_];
__device__ float g_B2[T_ * N_ * C_];
__device__ float g_B3[T_ * N_ * C_];
__device__ float g_B4[T_ * N_ * C_];
__device__ float g_B5[T_ * N_ * C_];
__device__ float g_BH[T_ * N_ * CH_];

// ---------------------------------------------------------------------------
// Helpers
// ---------------------------------------------------------------------------
__device__ __forceinline__ float warp_sum(float v) {
#pragma unroll
    for (int o = 16; o; o >>= 1) v += __shfl_xor_sync(0xffffffffu, v, o);
    return v;
}

// vectorized global float4 reduction (sm_90+)
__device__ __forceinline__ void red_add_v4(float* addr, float a, float b, float c, float d) {
    asm volatile("red.global.add.v4.f32 [%0], {%1,%2,%3,%4};"
                 :: "l"(addr), "f"(a), "f"(b), "f"(c), "f"(d)
                 : "memory");
}

// Block-wide (128-thread) LayerNorm finish: v is this channel's value.
__device__ __forceinline__ void ln_finish(float v, int c,
                                          const float* __restrict__ g,
                                          const float* __restrict__ be,
                                          float* __restrict__ outp, long idx) {
    __shared__ float red[8];
    float s1 = warp_sum(v);
    float s2 = warp_sum(v * v);
    int w = c >> 5;
    if ((c & 31) == 0) { red[w] = s1; red[4 + w] = s2; }
    __syncthreads();
    float sum = red[0] + red[1] + red[2] + red[3];
    float sq  = red[4] + red[5] + red[6] + red[7];
    float mu  = sum * (1.0f / 128.0f);
    float var = sq * (1.0f / 128.0f) - mu * mu;
    outp[idx] = (v - mu) * rsqrtf(var + 1e-5f) * g[c] + be[c];
}

// ---------------------------------------------------------------------------
// Degree / inverse degree
// ---------------------------------------------------------------------------
__global__ void k_deg(const int* __restrict__ ei, float* __restrict__ deg) {
    int e = blockIdx.x * blockDim.x + threadIdx.x;
    if (e < E_) atomicAdd(&deg[ei[E_ + e]], 1.0f);
}

__global__ void k_inv(const float* __restrict__ deg, float* __restrict__ inv) {
    int i = blockIdx.x * blockDim.x + threadIdx.x;
    if (i < N_) inv[i] = 1.0f / fmaxf(deg[i], 1.0f);
}

// ---------------------------------------------------------------------------
// Scatter-add of xin[t, src, :] (optionally * gate[t, src]) into out[t, dst, :]
// One warp-lane group of 32 handles one edge-row (32 float4s = 128 floats).
// ---------------------------------------------------------------------------
__global__ void k_scatter(const float* __restrict__ xin, const int* __restrict__ ei,
                          const float* __restrict__ gate, float* __restrict__ out) {
    long tid = (long)blockIdx.x * blockDim.x + threadIdx.x;
    int  c4  = (int)(tid & 31);
    long rest = tid >> 5;
    int  e = (int)(rest % E_);
    int  t = (int)(rest / E_);
    if (t >= T_) return;
    int s = ei[e];
    int d = ei[E_ + e];
    const float4 v = *(const float4*)(xin + ((long)t * N_ + s) * C_ + c4 * 4);
    float gmul = 1.0f;
    if (gate) gmul = gate[t * N_ + s];
    float* dst = out + ((long)t * N_ + d) * C_ + c4 * 4;
    red_add_v4(dst, v.x * gmul, v.y * gmul, v.z * gmul, v.w * gmul);
}

// ---------------------------------------------------------------------------
// SGEMM: Out[M,Ncol] = (A[M,Kd] * rowscale?) @ B[Kd,Ncol] + bias (+ GELU)
// Tile: BM=64, BN=128, BK=16; 256 threads; 4x8 register blocking.
// rowscale indexed by (row % N_) -> per-node inverse degree (segment mean fuse).
// ---------------------------------------------------------------------------
template <bool GELU>
__global__ __launch_bounds__(256)
void k_gemm(const float* __restrict__ A, const float* __restrict__ B,
            const float* __restrict__ bias, float* __restrict__ Out,
            int M, int Kd, int Ncol, const float* __restrict__ rowscale) {
    __shared__ float As[16][68];
    __shared__ float Bs[16][132];
    const int tid = threadIdx.x;
    const int m0 = blockIdx.y * 64;
    const int c0 = blockIdx.x * 128;
    const int ty = tid >> 4;
    const int tx = tid & 15;
    float acc[4][8];
#pragma unroll
    for (int i = 0; i < 4; i++)
#pragma unroll
        for (int j = 0; j < 8; j++) acc[i][j] = 0.0f;

    const int arow = tid >> 2;
    const int acol = (tid & 3) * 4;
    float ascale = 1.0f;
    if (rowscale) ascale = rowscale[(m0 + arow) % N_];
    const float* Ap = A + (long)(m0 + arow) * Kd + acol;
    const int brow = tid >> 4;
    const int bcol = (tid & 15) * 4;
    const float* Bp = B + (long)brow * Ncol + c0 + bcol;

    for (int kb = 0; kb < Kd; kb += 16) {
        float4 av = *(const float4*)(Ap + kb);
        As[acol + 0][arow] = av.x * ascale;
        As[acol + 1][arow] = av.y * ascale;
        As[acol + 2][arow] = av.z * ascale;
        As[acol + 3][arow] = av.w * ascale;
        float4 b0 = *(const float4*)(Bp + (long)kb * Ncol);
        float4 b1 = *(const float4*)(Bp + (long)kb * Ncol + 64);
        *(float4*)&Bs[brow][bcol] = b0;
        *(float4*)&Bs[brow][bcol + 64] = b1;
        __syncthreads();
#pragma unroll
        for (int kk = 0; kk < 16; kk++) {
            float4 a  = *(const float4*)&As[kk][ty * 4];
            float4 p0 = *(const float4*)&Bs[kk][tx * 4];
            float4 p1 = *(const float4*)&Bs[kk][64 + tx * 4];
            float av4[4] = {a.x, a.y, a.z, a.w};
            float bv[8]  = {p0.x, p0.y, p0.z, p0.w, p1.x, p1.y, p1.z, p1.w};
#pragma unroll
            for (int i = 0; i < 4; i++)
#pragma unroll
                for (int j = 0; j < 8; j++)
                    acc[i][j] = fmaf(av4[i], bv[j], acc[i][j]);
        }
        __syncthreads();
    }

    float bvals[8];
#pragma unroll
    for (int j = 0; j < 4; j++) {
        bvals[j]     = bias[c0 + tx * 4 + j];
        bvals[4 + j] = bias[c0 + 64 + tx * 4 + j];
    }
#pragma unroll
    for (int i = 0; i < 4; i++) {
        int row = m0 + ty * 4 + i;
        float o[8];
#pragma unroll
        for (int j = 0; j < 8; j++) {
            float v = acc[i][j] + bvals[j];
            if (GELU) {
                float v3 = v * v * v;
                v = 0.5f * v * (1.0f + tanhf(0.7978845608028654f * (v + 0.044715f * v3)));
            }
            o[j] = v;
        }
        float* op = Out + (long)row * Ncol + c0;
        *(float4*)(op + tx * 4)      = make_float4(o[0], o[1], o[2], o[3]);
        *(float4*)(op + 64 + tx * 4) = make_float4(o[4], o[5], o[6], o[7]);
    }
}

// ---------------------------------------------------------------------------
// out = LN(a + b) (one 128-thread block per (t,n) row)
// ---------------------------------------------------------------------------
__global__ void k_add_ln(const float* __restrict__ a, const float* __restrict__ b,
                         const float* __restrict__ g, const float* __restrict__ be,
                         float* __restrict__ out) {
    long row = blockIdx.x;
    int c = threadIdx.x;
    long idx = row * C_ + c;
    float v = a[idx] + b[idx];
    ln_finish(v, c, g, be, out, idx);
}

// ---------------------------------------------------------------------------
// x2 = LN(x1 + causal depthwise conv over time), fused
// ---------------------------------------------------------------------------
__global__ void k_conv_ln(const float* __restrict__ x1, const float* __restrict__ dk,
                          const float* __restrict__ g, const float* __restrict__ be,
                          float* __restrict__ out) {
    long row = blockIdx.x;
    int t = (int)(row / N_);
    int c = threadIdx.x;
    long idx = row * C_ + c;
    float v = x1[idx];
#pragma unroll
    for (int j = 0; j < K_; j++) {
        if (t - j >= 0) v += dk[c * K_ + j] * x1[idx - (long)j * N_ * C_];
    }
    ln_finish(v, c, g, be, out, idx);
}

// ---------------------------------------------------------------------------
// Time-windowed attention: one warp per (t, n, head); lane = channel-in-head.
// ---------------------------------------------------------------------------
__global__ void k_attn(const float* __restrict__ q, const float* __restrict__ k,
                       const float* __restrict__ v, const int* __restrict__ tix,
                       float* __restrict__ out) {
    long row = blockIdx.x;            // t*N + n
    int t = (int)(row / N_);
    int h = threadIdx.x >> 5;
    int d = threadIdx.x & 31;
    long base = row * C_ + h * DH_ + d;
    float qd = q[base];
    int ti_t = tix[t];
    float sc[WIN_];
#pragma unroll
    for (int w = 0; w < WIN_; w++) {
        int tp = t - w; if (tp < 0) tp = 0;
        bool ok = (t >= w) && ((ti_t - tix[tp]) < WIN_);
        float pr = 0.0f;
        if (t - w >= 0) pr = qd * k[base - (long)w * N_ * C_];
        float dot = warp_sum(pr) * 0.17677669529663687f;  // 1/sqrt(32)
        sc[w] = ok ? dot : -1e9f;
    }
    float mx = sc[0];
#pragma unroll
    for (int w = 1; w < WIN_; w++) mx = fmaxf(mx, sc[w]);
    float den = 0.0f, ex[WIN_];
#pragma unroll
    for (int w = 0; w < WIN_; w++) { ex[w] = expf(sc[w] - mx); den += ex[w]; }
    float o = 0.0f;
#pragma unroll
    for (int w = 0; w < WIN_; w++) {
        if (t - w >= 0) o += ex[w] * v[base - (long)w * N_ * C_];
    }
    out[base] = o / den;
}

// ---------------------------------------------------------------------------
// LIF scan over T (sequential, elementwise in (n,c)); fused spike gate for FFN.
// Forward value of straight-through spike == hard threshold.
// ---------------------------------------------------------------------------
__global__ void k_lif(const float* __restrict__ agg, float* __restrict__ spk_out,
                      float* __restrict__ ffn_in) {
    long i = (long)blockIdx.x * blockDim.x + threadIdx.x;
    if (i >= (long)N_ * C_) return;
    float vm = 0.0f;
#pragma unroll
    for (int t = 0; t < T_; t++) {
        long idx = (long)t * N_ * C_ + i;
        float a = agg[idx];
        float vn = 0.95f * vm + a;
        float s = (vn >= 1.0f) ? 1.0f : 0.0f;
        vm = vn * (1.0f - s);
        spk_out[idx] = s;
        ffn_in[idx]  = a * s;
    }
}

// ---------------------------------------------------------------------------
// spikes_hd.mean(-1) -> [T, N]
// ---------------------------------------------------------------------------
__global__ void k_spkmean(const float* __restrict__ spk, float* __restrict__ out) {
    long row = blockIdx.x;
    int c = threadIdx.x;
    float v = spk[row * C_ + c];
    __shared__ float red[4];
    float s = warp_sum(v);
    if ((c & 31) == 0) red[c >> 5] = s;
    __syncthreads();
    if (c == 0) out[row] = (red[0] + red[1] + red[2] + red[3]) * (1.0f / 128.0f);
}

// ---------------------------------------------------------------------------
// Launch
// ---------------------------------------------------------------------------
extern "C" void kernel_launch(void* const* d_in, const int* in_sizes, int n_in,
                              void* d_out, int out_size) {
    const float* x      = (const float*)d_in[0];
    const float* spikes = (const float*)d_in[1];
    const int*   ei     = (const int*)d_in[2];
    const int*   tix    = (const int*)d_in[3];
    const float* Ws  = (const float*)d_in[4];
    const float* bs  = (const float*)d_in[5];
    const float* dk  = (const float*)d_in[6];
    const float* g1  = (const float*)d_in[7];
    const float* b1  = (const float*)d_in[8];
    const float* g2  = (const float*)d_in[9];
    const float* b2  = (const float*)d_in[10];
    const float* gf  = (const float*)d_in[11];
    const float* bf  = (const float*)d_in[12];
    const float* Wq  = (const float*)d_in[13];
    const float* bq  = (const float*)d_in[14];
    const float* Wk  = (const float*)d_in[15];
    const float* bk  = (const float*)d_in[16];
    const float* Wv  = (const float*)d_in[17];
    const float* bv  = (const float*)d_in[18];
    const float* Wo  = (const float*)d_in[19];
    const float* bo  = (const float*)d_in[20];
    const float* f1w = (const float*)d_in[21];
    const float* f1b = (const float*)d_in[22];
    const float* f2w = (const float*)d_in[23];
    const float* f2b = (const float*)d_in[24];

    float *deg, *inv, *B1, *B2, *B3, *B4, *B5, *BH;
    cudaGetSymbolAddress((void**)&deg, g_deg);
    cudaGetSymbolAddress((void**)&inv, g_inv);
    cudaGetSymbolAddress((void**)&B1,  g_B1);
    cudaGetSymbolAddress((void**)&B2,  g_B2);
    cudaGetSymbolAddress((void**)&B3,  g_B3);
    cudaGetSymbolAddress((void**)&B4,  g_B4);
    cudaGetSymbolAddress((void**)&B5,  g_B5);
    cudaGetSymbolAddress((void**)&BH,  g_BH);

    const long tnc = (long)T_ * N_ * C_;
    const int  M   = T_ * N_;
    const int  SC_BLOCKS = (T_ * E_ * (C_ / 4)) / 256;  // exact

    // degrees
    cudaMemsetAsync(deg, 0, N_ * sizeof(float));
    k_deg<<<(E_ + 255) / 256, 256>>>(ei, deg);
    k_inv<<<(N_ + 255) / 256, 256>>>(deg, inv);

    // spatial GNN: mean-aggregate, @Ws + bs, residual + LN1
    cudaMemsetAsync(B1, 0, tnc * sizeof(float));
    k_scatter<<<SC_BLOCKS, 256>>>(x, ei, nullptr, B1);
    k_gemm<false><<<dim3(1, M / 64), 256>>>(B1, Ws, bs, B2, M, 128, 128, inv);
    k_add_ln<<<M, 128>>>(x, B2, g1, b1, B3);                 // x1 = B3

    // causal depthwise delay line + LN2
    k_conv_ln<<<M, 128>>>(B3, dk, g2, b2, B4);               // x2 = B4

    // spike-gated message mean
    cudaMemsetAsync(B1, 0, tnc * sizeof(float));
    k_scatter<<<SC_BLOCKS, 256>>>(B4, ei, spikes, B1);       // magg = B1

    // q/k/v projections (k, v get inverse-degree row scaling = segment mean)
    k_gemm<false><<<dim3(1, M / 64), 256>>>(B4, Wq, bq, B2, M, 128, 128, nullptr); // q = B2
    k_gemm<false><<<dim3(1, M / 64), 256>>>(B1, Wk, bk, B3, M, 128, 128, inv);     // k = B3
    k_gemm<false><<<dim3(1, M / 64), 256>>>(B1, Wv, bv, B5, M, 128, 128, inv);     // v = B5

    // windowed attention -> output projection
    k_attn<<<M, 128>>>(B2, B3, B5, tix, B1);                                       // attout = B1
    k_gemm<false><<<dim3(1, M / 64), 256>>>(B1, Wo, bo, B2, M, 128, 128, nullptr); // aggregated = B2

    // LIF scan + spike gate
    k_lif<<<(N_ * C_ + 255) / 256, 256>>>(B2, B3, B5);       // spikes_hd = B3, ffn_in = B5

    // FFN
    k_gemm<true><<<dim3(4, M / 64), 256>>>(B5, f1w, f1b, BH, M, 128, 512, nullptr);
    k_gemm<false><<<dim3(1, M / 64), 256>>>(BH, f2w, f2b, B1, M, 512, 128, nullptr); // ffn_out = B1

    // final residual + LN -> out_feat
    k_add_ln<<<M, 128>>>(B4, B1, gf, bf, (float*)d_out);

    // second output: spike mean over channels
    if (out_size >= (int)(tnc + (long)M))
        k_spkmean<<<M, 128>>>(B3, (float*)d_out + tnc);
}

// round 3
// speedup vs baseline: 1.7578x; 1.7578x over previous
#include <cuda_runtime.h>
#include <math.h>
#include <stdint.h>

// Problem constants
#define T_   8
#define N_   20000
#define C_   128
#define E_   320000
#define H_   4
#define DH_  32
#define WIN_ 4
#define K_   5
#define CH_  512
#define TN_  (T_ * N_)

// ---------------------------------------------------------------------------
// Scratch (__device__ globals; no cudaMalloc allowed)
// ---------------------------------------------------------------------------
__device__ float g_deg[N_];
__device__ float g_inv[N_];
__device__ float g_B1[T_ * N_ * C_];
__device__ float g_B2[T_ * N_ * C_];
__device__ float g_B3[T_ * N_ * C_];
__device__ float g_B4[T_ * N_ * C_];
__device__ float g_B5[T_ * N_ * C_];
__device__ float g_BH[T_ * N_ * CH_];
// transposed+tf32-converted weights: Ws,Wq,Wk,Wv,Wo (128x128), f1 (512x128), f2 (128x512)
__device__ float g_WT[5 * 128 * 128 + 512 * 128 + 128 * 512];

// ---------------------------------------------------------------------------
// Helpers
// ---------------------------------------------------------------------------
__device__ __forceinline__ uint32_t smem_u32(const void* p) {
    uint32_t a;
    asm("{ .reg .u64 t; cvta.to.shared.u64 t, %1; cvt.u32.u64 %0, t; }" : "=r"(a) : "l"(p));
    return a;
}
__device__ __forceinline__ float warp_sum(float v) {
#pragma unroll
    for (int o = 16; o; o >>= 1) v += __shfl_xor_sync(0xffffffffu, v, o);
    return v;
}
__device__ __forceinline__ void red_add_v4(float* addr, float a, float b, float c, float d) {
    asm volatile("red.global.add.v4.f32 [%0], {%1,%2,%3,%4};"
                 :: "l"(addr), "f"(a), "f"(b), "f"(c), "f"(d) : "memory");
}
__device__ __forceinline__ uint32_t f2tf(float v) {
    uint32_t u; asm("cvt.rna.tf32.f32 %0, %1;" : "=r"(u) : "f"(v)); return u;
}
__device__ __forceinline__ float gelu_t(float v) {
    float t = 0.7978845608028654f * (v + 0.044715f * v * v * v);
    float th; asm("tanh.approx.f32 %0, %1;" : "=f"(th) : "f"(t));
    return 0.5f * v * (1.0f + th);
}
__device__ __forceinline__ void cp16(uint32_t dst, const void* src) {
    asm volatile("cp.async.cg.shared.global [%0], [%1], 16;" :: "r"(dst), "l"(src));
}
#define CP_COMMIT() asm volatile("cp.async.commit_group;" ::: "memory")

__device__ __forceinline__ void mma_tf32(float* c, const uint32_t* a, uint32_t b0, uint32_t b1) {
    asm volatile("mma.sync.aligned.m16n8k8.row.col.f32.tf32.tf32.f32 "
                 "{%0,%1,%2,%3}, {%4,%5,%6,%7}, {%8,%9}, {%0,%1,%2,%3};"
                 : "+f"(c[0]), "+f"(c[1]), "+f"(c[2]), "+f"(c[3])
                 : "r"(a[0]), "r"(a[1]), "r"(a[2]), "r"(a[3]), "r"(b0), "r"(b1));
}

// ---------------------------------------------------------------------------
// Weight transpose + tf32 convert: out[n*K+k] = tf32(in[k*N+n])
// ---------------------------------------------------------------------------
__global__ void k_tcvt(const float* __restrict__ in, float* __restrict__ out,
                       int Kd, int Ncol) {
    __shared__ float tile[32][33];
    int kb = blockIdx.y * 32, nb = blockIdx.x * 32;
    int tx = threadIdx.x, ty = threadIdx.y;
#pragma unroll
    for (int j = 0; j < 32; j += 8)
        tile[ty + j][tx] = in[(long)(kb + ty + j) * Ncol + nb + tx];
    __syncthreads();
#pragma unroll
    for (int j = 0; j < 32; j += 8) {
        float v = tile[tx][ty + j];
        out[(long)(nb + ty + j) * Kd + kb + tx] = __uint_as_float(f2tf(v));
    }
}

// ---------------------------------------------------------------------------
// tf32 mma.sync GEMM: Out = epilogue( rowscale * (A @ BT^T) + bias )
// EPI: 0 = bias, 1 = bias+gelu, 2 = bias + residual + LayerNorm
// Block 128x128, BK=32, 256 threads (8 warps, 4(M)x2(N)), warp tile 32x64.
// cp.async 2-stage pipeline; SMEM ld = 36 words -> conflict-free fragments.
// ---------------------------------------------------------------------------
#define SA0   0
#define SA1   18432
#define SB0   36864
#define SB1   55296
#define SBIAS 73728
#define SG    74240
#define SBB   74752
#define SRED  75264
#define SMEM_GEMM (SRED + 2048)

template <int EPI>
__global__ __launch_bounds__(256)
void k_gemm_mma(const float* __restrict__ A, const float* __restrict__ BT,
                const float* __restrict__ bias, float* __restrict__ Out,
                int Kd, int ldout,
                const float* __restrict__ rowscale,
                const float* __restrict__ resid,
                const float* __restrict__ lng, const float* __restrict__ lnb) {
    extern __shared__ char smem[];
    uint32_t sbase = smem_u32(smem);
    const int tid = threadIdx.x;
    const int wid = tid >> 5, lane = tid & 31;
    const int g = lane >> 2, t = lane & 3;
    const int warp_m = wid & 3, warp_n = wid >> 2;
    const long m0 = (long)blockIdx.y * 128;
    const int  n0 = blockIdx.x * 128;

    float* sbias = (float*)(smem + SBIAS);
    float* sg    = (float*)(smem + SG);
    float* sbb   = (float*)(smem + SBB);
    float* sred1 = (float*)(smem + SRED);
    float* sred2 = (float*)(smem + SRED + 1024);

    if (tid < 128) {
        sbias[tid] = bias[n0 + tid];
        if (EPI == 2) { sg[tid] = lng[tid]; sbb[tid] = lnb[tid]; }
    }

    float c[2][8][4];
#pragma unroll
    for (int mt = 0; mt < 2; mt++)
#pragma unroll
        for (int nt = 0; nt < 8; nt++)
#pragma unroll
            for (int j = 0; j < 4; j++) c[mt][nt][j] = 0.0f;

    const int lrow = tid >> 3;
    const int lcol = (tid & 7) * 4;
    const int nck = Kd >> 5;

    // stage 0
    {
        uint32_t sa = sbase + SA0, sb = sbase + SB0;
#pragma unroll
        for (int i = 0; i < 4; i++) {
            int r = lrow + 32 * i;
            cp16(sa + (uint32_t)(r * 36 + lcol) * 4, A  + (m0 + r) * Kd + lcol);
            cp16(sb + (uint32_t)(r * 36 + lcol) * 4, BT + (long)(n0 + r) * Kd + lcol);
        }
        CP_COMMIT();
    }

    for (int ck = 0; ck < nck; ck++) {
        if (ck + 1 < nck) {
            int buf = (ck + 1) & 1;
            uint32_t sa = sbase + (buf ? SA1 : SA0);
            uint32_t sb = sbase + (buf ? SB1 : SB0);
            long kb = (long)(ck + 1) * 32;
#pragma unroll
            for (int i = 0; i < 4; i++) {
                int r = lrow + 32 * i;
                cp16(sa + (uint32_t)(r * 36 + lcol) * 4, A  + (m0 + r) * Kd + kb + lcol);
                cp16(sb + (uint32_t)(r * 36 + lcol) * 4, BT + (long)(n0 + r) * Kd + kb + lcol);
            }
            CP_COMMIT();
            asm volatile("cp.async.wait_group 1;" ::: "memory");
        } else {
            asm volatile("cp.async.wait_group 0;" ::: "memory");
        }
        __syncthreads();

        const float* As = (const float*)(smem + ((ck & 1) ? SA1 : SA0));
        const float* Bs = (const float*)(smem + ((ck & 1) ? SB1 : SB0));
#pragma unroll
        for (int ks = 0; ks < 4; ks++) {
            int k0 = ks * 8 + t;
            uint32_t a[2][4];
#pragma unroll
            for (int mt = 0; mt < 2; mt++) {
                const float* ap = As + (warp_m * 32 + mt * 16 + g) * 36 + k0;
                a[mt][0] = f2tf(ap[0]);
                a[mt][1] = f2tf(ap[8 * 36]);
                a[mt][2] = f2tf(ap[4]);
                a[mt][3] = f2tf(ap[8 * 36 + 4]);
            }
#pragma unroll
            for (int nt = 0; nt < 8; nt++) {
                const float* bp = Bs + (warp_n * 64 + nt * 8 + g) * 36 + k0;
                uint32_t b0 = __float_as_uint(bp[0]);
                uint32_t b1 = __float_as_uint(bp[4]);
#pragma unroll
                for (int mt = 0; mt < 2; mt++) mma_tf32(c[mt][nt], a[mt], b0, b1);
            }
        }
        __syncthreads();
    }

    // ---------------- epilogue ----------------
    if (EPI == 2) {
        // pass 1: value = rowscale*acc + bias + resid; row sums via quad shuffle
#pragma unroll
        for (int mt = 0; mt < 2; mt++) {
#pragma unroll
            for (int h = 0; h < 2; h++) {
                int rib = warp_m * 32 + mt * 16 + h * 8 + g;
                long gr = m0 + rib;
                float s = rowscale ? rowscale[(int)(gr % N_)] : 1.0f;
                float s1 = 0.f, s2 = 0.f;
#pragma unroll
                for (int nt = 0; nt < 8; nt++) {
                    int col = warp_n * 64 + nt * 8 + 2 * t;
                    float2 rv = *(const float2*)(resid + gr * 128 + col);
                    float v0 = c[mt][nt][h * 2 + 0] * s + sbias[col]     + rv.x;
                    float v1 = c[mt][nt][h * 2 + 1] * s + sbias[col + 1] + rv.y;
                    c[mt][nt][h * 2 + 0] = v0;
                    c[mt][nt][h * 2 + 1] = v1;
                    s1 += v0 + v1;
                    s2 += v0 * v0 + v1 * v1;
                }
                s1 += __shfl_xor_sync(0xffffffffu, s1, 1);
                s1 += __shfl_xor_sync(0xffffffffu, s1, 2);
                s2 += __shfl_xor_sync(0xffffffffu, s2, 1);
                s2 += __shfl_xor_sync(0xffffffffu, s2, 2);
                if (t == 0) {
                    sred1[rib * 2 + warp_n] = s1;
                    sred2[rib * 2 + warp_n] = s2;
                }
            }
        }
        __syncthreads();
        // pass 2: LN normalize + store
#pragma unroll
        for (int mt = 0; mt < 2; mt++) {
#pragma unroll
            for (int h = 0; h < 2; h++) {
                int rib = warp_m * 32 + mt * 16 + h * 8 + g;
                long gr = m0 + rib;
                float s1 = sred1[rib * 2] + sred1[rib * 2 + 1];
                float s2 = sred2[rib * 2] + sred2[rib * 2 + 1];
                float mu = s1 * (1.0f / 128.0f);
                float var = s2 * (1.0f / 128.0f) - mu * mu;
                float rs = rsqrtf(var + 1e-5f);
#pragma unroll
                for (int nt = 0; nt < 8; nt++) {
                    int col = warp_n * 64 + nt * 8 + 2 * t;
                    float o0 = (c[mt][nt][h * 2 + 0] - mu) * rs * sg[col]     + sbb[col];
                    float o1 = (c[mt][nt][h * 2 + 1] - mu) * rs * sg[col + 1] + sbb[col + 1];
                    *(float2*)(Out + gr * 128 + col) = make_float2(o0, o1);
                }
            }
        }
    } else {
#pragma unroll
        for (int mt = 0; mt < 2; mt++) {
#pragma unroll
            for (int h = 0; h < 2; h++) {
                long gr = m0 + warp_m * 32 + mt * 16 + h * 8 + g;
                float s = rowscale ? rowscale[(int)(gr % N_)] : 1.0f;
#pragma unroll
                for (int nt = 0; nt < 8; nt++) {
                    int col = warp_n * 64 + nt * 8 + 2 * t;
                    float v0 = c[mt][nt][h * 2 + 0] * s + sbias[col];
                    float v1 = c[mt][nt][h * 2 + 1] * s + sbias[col + 1];
                    if (EPI == 1) { v0 = gelu_t(v0); v1 = gelu_t(v1); }
                    *(float2*)(Out + gr * (long)ldout + n0 + col) = make_float2(v0, v1);
                }
            }
        }
    }
}

// ---------------------------------------------------------------------------
// Degree / inverse degree
// ---------------------------------------------------------------------------
__global__ void k_deg(const int* __restrict__ ei, float* __restrict__ deg) {
    int e = blockIdx.x * blockDim.x + threadIdx.x;
    if (e < E_) atomicAdd(&deg[ei[E_ + e]], 1.0f);
}
__global__ void k_inv(const float* __restrict__ deg, float* __restrict__ inv) {
    int i = blockIdx.x * blockDim.x + threadIdx.x;
    if (i < N_) inv[i] = 1.0f / fmaxf(deg[i], 1.0f);
}

// ---------------------------------------------------------------------------
// Scatter-add of xin[t, src, :] (optionally * gate[t, src]) into out[t, dst, :]
// ---------------------------------------------------------------------------
__global__ void k_scatter(const float* __restrict__ xin, const int* __restrict__ ei,
                          const float* __restrict__ gate, float* __restrict__ out) {
    long tid = (long)blockIdx.x * blockDim.x + threadIdx.x;
    int  c4 = (int)(tid & 31);
    long rest = tid >> 5;
    int  e = (int)(rest % E_);
    int  t = (int)(rest / E_);
    if (t >= T_) return;
    int s = ei[e];
    int d = ei[E_ + e];
    const float4 v = *(const float4*)(xin + ((long)t * N_ + s) * C_ + c4 * 4);
    float gmul = 1.0f;
    if (gate) gmul = gate[t * N_ + s];
    float* dst = out + ((long)t * N_ + d) * C_ + c4 * 4;
    red_add_v4(dst, v.x * gmul, v.y * gmul, v.z * gmul, v.w * gmul);
}

// ---------------------------------------------------------------------------
// x2 = LN(x1 + causal depthwise conv over time)
// ---------------------------------------------------------------------------
__global__ void k_conv_ln(const float* __restrict__ x1, const float* __restrict__ dk,
                          const float* __restrict__ g, const float* __restrict__ be,
                          float* __restrict__ out) {
    long row = blockIdx.x;
    int t = (int)(row / N_);
    int c = threadIdx.x;
    long idx = row * C_ + c;
    float v = x1[idx];
#pragma unroll
    for (int j = 0; j < K_; j++)
        if (t - j >= 0) v += dk[c * K_ + j] * x1[idx - (long)j * N_ * C_];
    __shared__ float red[8];
    float s1 = warp_sum(v), s2 = warp_sum(v * v);
    int w = c >> 5;
    if ((c & 31) == 0) { red[w] = s1; red[4 + w] = s2; }
    __syncthreads();
    float sum = red[0] + red[1] + red[2] + red[3];
    float sq  = red[4] + red[5] + red[6] + red[7];
    float mu = sum * (1.0f / 128.0f);
    float var = sq * (1.0f / 128.0f) - mu * mu;
    out[idx] = (v - mu) * rsqrtf(var + 1e-5f) * g[c] + be[c];
}

// ---------------------------------------------------------------------------
// Time-windowed attention: one warp per (t, n, head)
// ---------------------------------------------------------------------------
__global__ void k_attn(const float* __restrict__ q, const float* __restrict__ k,
                       const float* __restrict__ v, const int* __restrict__ tix,
                       float* __restrict__ out) {
    long row = blockIdx.x;
    int t = (int)(row / N_);
    int h = threadIdx.x >> 5;
    int d = threadIdx.x & 31;
    long base = row * C_ + h * DH_ + d;
    float qd = q[base];
    int ti_t = tix[t];
    float sc[WIN_];
#pragma unroll
    for (int w = 0; w < WIN_; w++) {
        int tp = t - w; if (tp < 0) tp = 0;
        bool ok = (t >= w) && ((ti_t - tix[tp]) < WIN_);
        float pr = 0.0f;
        if (t - w >= 0) pr = qd * k[base - (long)w * N_ * C_];
        float dot = warp_sum(pr) * 0.17677669529663687f;
        sc[w] = ok ? dot : -1e9f;
    }
    float mx = sc[0];
#pragma unroll
    for (int w = 1; w < WIN_; w++) mx = fmaxf(mx, sc[w]);
    float den = 0.0f, ex[WIN_];
#pragma unroll
    for (int w = 0; w < WIN_; w++) { ex[w] = expf(sc[w] - mx); den += ex[w]; }
    float o = 0.0f;
#pragma unroll
    for (int w = 0; w < WIN_; w++)
        if (t - w >= 0) o += ex[w] * v[base - (long)w * N_ * C_];
    out[base] = o / den;
}

// ---------------------------------------------------------------------------
// LIF scan over T + spike gate
// ---------------------------------------------------------------------------
__global__ void k_lif(const float* __restrict__ agg, float* __restrict__ spk_out,
                      float* __restrict__ ffn_in) {
    long i = (long)blockIdx.x * blockDim.x + threadIdx.x;
    if (i >= (long)N_ * C_) return;
    float vm = 0.0f;
#pragma unroll
    for (int t = 0; t < T_; t++) {
        long idx = (long)t * N_ * C_ + i;
        float a = agg[idx];
        float vn = 0.95f * vm + a;
        float s = (vn >= 1.0f) ? 1.0f : 0.0f;
        vm = vn * (1.0f - s);
        spk_out[idx] = s;
        ffn_in[idx]  = a * s;
    }
}

// ---------------------------------------------------------------------------
// spikes_hd.mean(-1) -> [T, N]
// ---------------------------------------------------------------------------
__global__ void k_spkmean(const float* __restrict__ spk, float* __restrict__ out) {
    long row = blockIdx.x;
    int c = threadIdx.x;
    float v = spk[row * C_ + c];
    __shared__ float red[4];
    float s = warp_sum(v);
    if ((c & 31) == 0) red[c >> 5] = s;
    __syncthreads();
    if (c == 0) out[row] = (red[0] + red[1] + red[2] + red[3]) * (1.0f / 128.0f);
}

// ---------------------------------------------------------------------------
// Launch
// ---------------------------------------------------------------------------
extern "C" void kernel_launch(void* const* d_in, const int* in_sizes, int n_in,
                              void* d_out, int out_size) {
    const float* x      = (const float*)d_in[0];
    const float* spikes = (const float*)d_in[1];
    const int*   ei     = (const int*)d_in[2];
    const int*   tix    = (const int*)d_in[3];
    const float* Ws  = (const float*)d_in[4];
    const float* bs  = (const float*)d_in[5];
    const float* dk  = (const float*)d_in[6];
    const float* g1  = (const float*)d_in[7];
    const float* b1  = (const float*)d_in[8];
    const float* g2  = (const float*)d_in[9];
    const float* b2  = (const float*)d_in[10];
    const float* gf  = (const float*)d_in[11];
    const float* bf  = (const float*)d_in[12];
    const float* Wq  = (const float*)d_in[13];
    const float* bq  = (const float*)d_in[14];
    const float* Wk  = (const float*)d_in[15];
    const float* bk  = (const float*)d_in[16];
    const float* Wv  = (const float*)d_in[17];
    const float* bv  = (const float*)d_in[18];
    const float* Wo  = (const float*)d_in[19];
    const float* bo  = (const float*)d_in[20];
    const float* f1w = (const float*)d_in[21];
    const float* f1b = (const float*)d_in[22];
    const float* f2w = (const float*)d_in[23];
    const float* f2b = (const float*)d_in[24];

    float *deg, *inv, *B1, *B2, *B3, *B4, *B5, *BH, *WT;
    cudaGetSymbolAddress((void**)&deg, g_deg);
    cudaGetSymbolAddress((void**)&inv, g_inv);
    cudaGetSymbolAddress((void**)&B1,  g_B1);
    cudaGetSymbolAddress((void**)&B2,  g_B2);
    cudaGetSymbolAddress((void**)&B3,  g_B3);
    cudaGetSymbolAddress((void**)&B4,  g_B4);
    cudaGetSymbolAddress((void**)&B5,  g_B5);
    cudaGetSymbolAddress((void**)&BH,  g_BH);
    cudaGetSymbolAddress((void**)&WT,  g_WT);

    cudaFuncSetAttribute(k_gemm_mma<0>, cudaFuncAttributeMaxDynamicSharedMemorySize, SMEM_GEMM);
    cudaFuncSetAttribute(k_gemm_mma<1>, cudaFuncAttributeMaxDynamicSharedMemorySize, SMEM_GEMM);
    cudaFuncSetAttribute(k_gemm_mma<2>, cudaFuncAttributeMaxDynamicSharedMemorySize, SMEM_GEMM);

    float* WsT = WT;
    float* WqT = WT + 16384;
    float* WkT = WT + 32768;
    float* WvT = WT + 49152;
    float* WoT = WT + 65536;
    float* f1T = WT + 81920;    // 512 x 128
    float* f2T = WT + 147456;   // 128 x 512

    const long tnc = (long)T_ * N_ * C_;
    const int  SC_BLOCKS = (T_ * E_ * (C_ / 4)) / 256;
    const dim3 tb(32, 8);

    // one-time per launch: weight transposes + tf32 convert
    k_tcvt<<<dim3(4, 4),  tb>>>(Ws,  WsT, 128, 128);
    k_tcvt<<<dim3(4, 4),  tb>>>(Wq,  WqT, 128, 128);
    k_tcvt<<<dim3(4, 4),  tb>>>(Wk,  WkT, 128, 128);
    k_tcvt<<<dim3(4, 4),  tb>>>(Wv,  WvT, 128, 128);
    k_tcvt<<<dim3(4, 4),  tb>>>(Wo,  WoT, 128, 128);
    k_tcvt<<<dim3(16, 4), tb>>>(f1w, f1T, 128, 512);
    k_tcvt<<<dim3(4, 16), tb>>>(f2w, f2T, 512, 128);

    // degrees
    cudaMemsetAsync(deg, 0, N_ * sizeof(float));
    k_deg<<<(E_ + 255) / 256, 256>>>(ei, deg);
    k_inv<<<(N_ + 255) / 256, 256>>>(deg, inv);

    // spatial GNN: sum-aggregate -> GEMM(Ws) w/ rowscale(inv) + residual(x) + LN1 -> x1=B3
    cudaMemsetAsync(B1, 0, tnc * sizeof(float));
    k_scatter<<<SC_BLOCKS, 256>>>(x, ei, nullptr, B1);
    k_gemm_mma<2><<<dim3(1, 1250), 256, SMEM_GEMM>>>(B1, WsT, bs, B3, 128, 128, inv, x, g1, b1);

    // causal depthwise delay line + LN2 -> x2=B4
    k_conv_ln<<<TN_, 128>>>(B3, dk, g2, b2, B4);

    // spike-gated message sum -> B1
    cudaMemsetAsync(B1, 0, tnc * sizeof(float));
    k_scatter<<<SC_BLOCKS, 256>>>(B4, ei, spikes, B1);

    // q/k/v projections (k, v get inverse-degree rowscale in epilogue)
    k_gemm_mma<0><<<dim3(1, 1250), 256, SMEM_GEMM>>>(B4, WqT, bq, B2, 128, 128, nullptr, nullptr, nullptr, nullptr); // q=B2
    k_gemm_mma<0><<<dim3(1, 1250), 256, SMEM_GEMM>>>(B1, WkT, bk, B3, 128, 128, inv, nullptr, nullptr, nullptr);     // k=B3
    k_gemm_mma<0><<<dim3(1, 1250), 256, SMEM_GEMM>>>(B1, WvT, bv, B5, 128, 128, inv, nullptr, nullptr, nullptr);     // v=B5

    // windowed attention -> Wo projection
    k_attn<<<TN_, 128>>>(B2, B3, B5, tix, B1);                                                                        // attout=B1
    k_gemm_mma<0><<<dim3(1, 1250), 256, SMEM_GEMM>>>(B1, WoT, bo, B2, 128, 128, nullptr, nullptr, nullptr, nullptr);  // aggregated=B2

    // LIF scan + spike gate
    k_lif<<<(N_ * C_ + 255) / 256, 256>>>(B2, B3, B5);  // spikes_hd=B3, ffn_in=B5

    // FFN: fc1 fused GELU; fc2 fused residual(x2)+LNf -> d_out
    k_gemm_mma<1><<<dim3(4, 1250), 256, SMEM_GEMM>>>(B5, f1T, f1b, BH, 128, 512, nullptr, nullptr, nullptr, nullptr);
    k_gemm_mma<2><<<dim3(1, 1250), 256, SMEM_GEMM>>>(BH, f2T, f2b, (float*)d_out, 512, 128, nullptr, B4, gf, bf);

    // second output: spike mean over channels
    if (out_size >= (int)(tnc + (long)TN_))
        k_spkmean<<<TN_, 128>>>(B3, (float*)d_out + tnc);
}

// round 4
// speedup vs baseline: 2.4990x; 1.4216x over previous
#include <cuda_runtime.h>
#include <math.h>
#include <stdint.h>

// Problem constants
#define T_   8
#define N_   20000
#define C_   128
#define E_   320000
#define H_   4
#define DH_  32
#define WIN_ 4
#define K_   5
#define CH_  512
#define TN_  (T_ * N_)

// ---------------------------------------------------------------------------
// Scratch (__device__ globals; no cudaMalloc allowed)
// ---------------------------------------------------------------------------
__device__ float g_inv[N_];
__device__ int   g_cnt[N_];
__device__ int   g_off[N_ + 1];
__device__ int   g_cur[N_];
__device__ int   g_srcs[E_];
__device__ float g_B1[T_ * N_ * C_];
__device__ float g_B2[T_ * N_ * C_];
__device__ float g_B3[T_ * N_ * C_];
__device__ float g_B4[T_ * N_ * C_];
__device__ float g_B5[T_ * N_ * C_];
// transposed+tf32-converted weights: Ws,Wq,Wk,Wv,Wo (128x128), f1 (512x128), f2 (128x512)
__device__ float g_WT[5 * 128 * 128 + 512 * 128 + 128 * 512];

// ---------------------------------------------------------------------------
// Helpers
// ---------------------------------------------------------------------------
__device__ __forceinline__ uint32_t smem_u32(const void* p) {
    uint32_t a;
    asm("{ .reg .u64 t; cvta.to.shared.u64 t, %1; cvt.u32.u64 %0, t; }" : "=r"(a) : "l"(p));
    return a;
}
__device__ __forceinline__ float warp_sum(float v) {
#pragma unroll
    for (int o = 16; o; o >>= 1) v += __shfl_xor_sync(0xffffffffu, v, o);
    return v;
}
__device__ __forceinline__ uint32_t f2tf(float v) {
    uint32_t u; asm("cvt.rna.tf32.f32 %0, %1;" : "=r"(u) : "f"(v)); return u;
}
__device__ __forceinline__ float gelu_t(float v) {
    float t = 0.7978845608028654f * (v + 0.044715f * v * v * v);
    float th; asm("tanh.approx.f32 %0, %1;" : "=f"(th) : "f"(t));
    return 0.5f * v * (1.0f + th);
}
__device__ __forceinline__ void cp16(uint32_t dst, const void* src) {
    asm volatile("cp.async.cg.shared.global [%0], [%1], 16;" :: "r"(dst), "l"(src));
}
#define CP_COMMIT() asm volatile("cp.async.commit_group;" ::: "memory")
#define CP_WAIT0()  asm volatile("cp.async.wait_group 0;" ::: "memory")
#define CP_WAIT1()  asm volatile("cp.async.wait_group 1;" ::: "memory")

__device__ __forceinline__ void mma_tf32(float* c, const uint32_t* a, uint32_t b0, uint32_t b1) {
    asm volatile("mma.sync.aligned.m16n8k8.row.col.f32.tf32.tf32.f32 "
                 "{%0,%1,%2,%3}, {%4,%5,%6,%7}, {%8,%9}, {%0,%1,%2,%3};"
                 : "+f"(c[0]), "+f"(c[1]), "+f"(c[2]), "+f"(c[3])
                 : "r"(a[0]), "r"(a[1]), "r"(a[2]), "r"(a[3]), "r"(b0), "r"(b1));
}

// ---------------------------------------------------------------------------
// Weight transpose + tf32 convert: out[n*K+k] = tf32(in[k*N+n])
// ---------------------------------------------------------------------------
__global__ void k_tcvt(const float* __restrict__ in, float* __restrict__ out,
                       int Kd, int Ncol) {
    __shared__ float tile[32][33];
    int kb = blockIdx.y * 32, nb = blockIdx.x * 32;
    int tx = threadIdx.x, ty = threadIdx.y;
#pragma unroll
    for (int j = 0; j < 32; j += 8)
        tile[ty + j][tx] = in[(long)(kb + ty + j) * Ncol + nb + tx];
    __syncthreads();
#pragma unroll
    for (int j = 0; j < 32; j += 8) {
        float v = tile[tx][ty + j];
        out[(long)(nb + ty + j) * Kd + kb + tx] = __uint_as_float(f2tf(v));
    }
}

// ---------------------------------------------------------------------------
// CSR build: histogram -> scan -> fill
// ---------------------------------------------------------------------------
__global__ void k_hist(const int* __restrict__ ei, int* __restrict__ cnt) {
    int e = blockIdx.x * blockDim.x + threadIdx.x;
    if (e < E_) atomicAdd(&cnt[ei[E_ + e]], 1);
}

__global__ void k_scan(const int* __restrict__ cnt, int* __restrict__ off,
                       int* __restrict__ cur, float* __restrict__ inv) {
    __shared__ int wsum[32];
    __shared__ int sbase;
    __shared__ int stot;
    if (threadIdx.x == 0) sbase = 0;
    __syncthreads();
    int lane = threadIdx.x & 31, w = threadIdx.x >> 5;
    for (int start = 0; start < N_; start += 1024) {
        int i = start + threadIdx.x;
        int v = (i < N_) ? cnt[i] : 0;
        int s = v;
#pragma unroll
        for (int o = 1; o < 32; o <<= 1) {
            int tmp = __shfl_up_sync(0xffffffffu, s, o);
            if (lane >= o) s += tmp;
        }
        if (lane == 31) wsum[w] = s;
        __syncthreads();
        if (w == 0) {
            int ws = wsum[lane];
#pragma unroll
            for (int o = 1; o < 32; o <<= 1) {
                int tmp = __shfl_up_sync(0xffffffffu, ws, o);
                if (lane >= o) ws += tmp;
            }
            wsum[lane] = ws;
            if (lane == 31) stot = ws;
        }
        __syncthreads();
        int incl = s + (w > 0 ? wsum[w - 1] : 0) + sbase;
        if (i < N_) {
            int excl = incl - v;
            off[i] = excl;
            cur[i] = excl;
            inv[i] = 1.0f / fmaxf((float)v, 1.0f);
        }
        __syncthreads();
        if (threadIdx.x == 0) sbase += stot;
        __syncthreads();
    }
    if (threadIdx.x == 0) off[N_] = sbase;
}

__global__ void k_fill(const int* __restrict__ ei, int* __restrict__ cur,
                       int* __restrict__ srcs) {
    int e = blockIdx.x * blockDim.x + threadIdx.x;
    if (e >= E_) return;
    int d = ei[E_ + e];
    int idx = atomicAdd(&cur[d], 1);
    srcs[idx] = ei[e];
}

// ---------------------------------------------------------------------------
// Gather-mean: out[t,n,:] = inv[n] * sum_{e: dst=n} gate[t,src]*xin[t,src,:]
// One warp per (t,n); lane handles one float4 (4 channels).
// ---------------------------------------------------------------------------
template <bool GATED>
__global__ void k_gather(const float* __restrict__ xin, const int* __restrict__ off,
                         const int* __restrict__ srcs, const float* __restrict__ gate,
                         const float* __restrict__ inv, float* __restrict__ out) {
    int gw = (int)((blockIdx.x * blockDim.x + threadIdx.x) >> 5);
    int lane = threadIdx.x & 31;
    if (gw >= TN_) return;
    int t = gw / N_, n = gw - t * N_;
    int s0 = off[n], s1 = off[n + 1];
    const float* xt = xin + (long)t * N_ * C_;
    const float* gt = gate + (long)t * N_;
    float ax = 0.f, ay = 0.f, az = 0.f, aw = 0.f;
    for (int j = s0; j < s1; j++) {
        int s = srcs[j];
        float4 v = *(const float4*)(xt + (long)s * C_ + lane * 4);
        if (GATED) {
            float gm = gt[s];
            ax += v.x * gm; ay += v.y * gm; az += v.z * gm; aw += v.w * gm;
        } else {
            ax += v.x; ay += v.y; az += v.z; aw += v.w;
        }
    }
    float iv = inv[n];
    *(float4*)(out + (long)gw * C_ + lane * 4) = make_float4(ax * iv, ay * iv, az * iv, aw * iv);
}

// ---------------------------------------------------------------------------
// tf32 mma.sync GEMM: Out = epilogue( (A @ BT^T) + bias )
// EPI: 0 = bias, 2 = bias + residual + LayerNorm
// Block 128x128, BK=32, 256 threads (8 warps, 4(M)x2(N)), warp tile 32x64.
// ---------------------------------------------------------------------------
#define SA0   0
#define SA1   18432
#define SB0   36864
#define SB1   55296
#define SBIAS 73728
#define SG    74240
#define SBB   74752
#define SRED  75264
#define SMEM_GEMM (SRED + 2048)

template <int EPI>
__global__ __launch_bounds__(256)
void k_gemm_mma(const float* __restrict__ A, const float* __restrict__ BT,
                const float* __restrict__ bias, float* __restrict__ Out,
                int Kd, int ldout,
                const float* __restrict__ resid,
                const float* __restrict__ lng, const float* __restrict__ lnb) {
    extern __shared__ char smem[];
    uint32_t sbase = smem_u32(smem);
    const int tid = threadIdx.x;
    const int wid = tid >> 5, lane = tid & 31;
    const int g = lane >> 2, t = lane & 3;
    const int warp_m = wid & 3, warp_n = wid >> 2;
    const long m0 = (long)blockIdx.y * 128;
    const int  n0 = blockIdx.x * 128;

    float* sbias = (float*)(smem + SBIAS);
    float* sg    = (float*)(smem + SG);
    float* sbb   = (float*)(smem + SBB);
    float* sred1 = (float*)(smem + SRED);
    float* sred2 = (float*)(smem + SRED + 1024);

    if (tid < 128) {
        sbias[tid] = bias[n0 + tid];
        if (EPI == 2) { sg[tid] = lng[tid]; sbb[tid] = lnb[tid]; }
    }

    float c[2][8][4];
#pragma unroll
    for (int mt = 0; mt < 2; mt++)
#pragma unroll
        for (int nt = 0; nt < 8; nt++)
#pragma unroll
            for (int j = 0; j < 4; j++) c[mt][nt][j] = 0.0f;

    const int lrow = tid >> 3;
    const int lcol = (tid & 7) * 4;
    const int nck = Kd >> 5;

    {
        uint32_t sa = sbase + SA0, sb = sbase + SB0;
#pragma unroll
        for (int i = 0; i < 4; i++) {
            int r = lrow + 32 * i;
            cp16(sa + (uint32_t)(r * 36 + lcol) * 4, A  + (m0 + r) * Kd + lcol);
            cp16(sb + (uint32_t)(r * 36 + lcol) * 4, BT + (long)(n0 + r) * Kd + lcol);
        }
        CP_COMMIT();
    }

    for (int ck = 0; ck < nck; ck++) {
        if (ck + 1 < nck) {
            int buf = (ck + 1) & 1;
            uint32_t sa = sbase + (buf ? SA1 : SA0);
            uint32_t sb = sbase + (buf ? SB1 : SB0);
            long kb = (long)(ck + 1) * 32;
#pragma unroll
            for (int i = 0; i < 4; i++) {
                int r = lrow + 32 * i;
                cp16(sa + (uint32_t)(r * 36 + lcol) * 4, A  + (m0 + r) * Kd + kb + lcol);
                cp16(sb + (uint32_t)(r * 36 + lcol) * 4, BT + (long)(n0 + r) * Kd + kb + lcol);
            }
            CP_COMMIT();
            CP_WAIT1();
        } else {
            CP_WAIT0();
        }
        __syncthreads();

        const float* As = (const float*)(smem + ((ck & 1) ? SA1 : SA0));
        const float* Bs = (const float*)(smem + ((ck & 1) ? SB1 : SB0));
#pragma unroll
        for (int ks = 0; ks < 4; ks++) {
            int k0 = ks * 8 + t;
            uint32_t a[2][4];
#pragma unroll
            for (int mt = 0; mt < 2; mt++) {
                const float* ap = As + (warp_m * 32 + mt * 16 + g) * 36 + k0;
                a[mt][0] = f2tf(ap[0]);
                a[mt][1] = f2tf(ap[8 * 36]);
                a[mt][2] = f2tf(ap[4]);
                a[mt][3] = f2tf(ap[8 * 36 + 4]);
            }
#pragma unroll
            for (int nt = 0; nt < 8; nt++) {
                const float* bp = Bs + (warp_n * 64 + nt * 8 + g) * 36 + k0;
                uint32_t b0 = __float_as_uint(bp[0]);
                uint32_t b1 = __float_as_uint(bp[4]);
#pragma unroll
                for (int mt = 0; mt < 2; mt++) mma_tf32(c[mt][nt], a[mt], b0, b1);
            }
        }
        __syncthreads();
    }

    if (EPI == 2) {
#pragma unroll
        for (int mt = 0; mt < 2; mt++) {
#pragma unroll
            for (int h = 0; h < 2; h++) {
                int rib = warp_m * 32 + mt * 16 + h * 8 + g;
                long gr = m0 + rib;
                float s1 = 0.f, s2 = 0.f;
#pragma unroll
                for (int nt = 0; nt < 8; nt++) {
                    int col = warp_n * 64 + nt * 8 + 2 * t;
                    float2 rv = *(const float2*)(resid + gr * 128 + col);
                    float v0 = c[mt][nt][h * 2 + 0] + sbias[col]     + rv.x;
                    float v1 = c[mt][nt][h * 2 + 1] + sbias[col + 1] + rv.y;
                    c[mt][nt][h * 2 + 0] = v0;
                    c[mt][nt][h * 2 + 1] = v1;
                    s1 += v0 + v1;
                    s2 += v0 * v0 + v1 * v1;
                }
                s1 += __shfl_xor_sync(0xffffffffu, s1, 1);
                s1 += __shfl_xor_sync(0xffffffffu, s1, 2);
                s2 += __shfl_xor_sync(0xffffffffu, s2, 1);
                s2 += __shfl_xor_sync(0xffffffffu, s2, 2);
                if (t == 0) {
                    sred1[rib * 2 + warp_n] = s1;
                    sred2[rib * 2 + warp_n] = s2;
                }
            }
        }
        __syncthreads();
#pragma unroll
        for (int mt = 0; mt < 2; mt++) {
#pragma unroll
            for (int h = 0; h < 2; h++) {
                int rib = warp_m * 32 + mt * 16 + h * 8 + g;
                long gr = m0 + rib;
                float s1 = sred1[rib * 2] + sred1[rib * 2 + 1];
                float s2 = sred2[rib * 2] + sred2[rib * 2 + 1];
                float mu = s1 * (1.0f / 128.0f);
                float var = s2 * (1.0f / 128.0f) - mu * mu;
                float rs = rsqrtf(var + 1e-5f);
#pragma unroll
                for (int nt = 0; nt < 8; nt++) {
                    int col = warp_n * 64 + nt * 8 + 2 * t;
                    float o0 = (c[mt][nt][h * 2 + 0] - mu) * rs * sg[col]     + sbb[col];
                    float o1 = (c[mt][nt][h * 2 + 1] - mu) * rs * sg[col + 1] + sbb[col + 1];
                    *(float2*)(Out + gr * 128 + col) = make_float2(o0, o1);
                }
            }
        }
    } else {
#pragma unroll
        for (int mt = 0; mt < 2; mt++) {
#pragma unroll
            for (int h = 0; h < 2; h++) {
                long gr = m0 + warp_m * 32 + mt * 16 + h * 8 + g;
#pragma unroll
                for (int nt = 0; nt < 8; nt++) {
                    int col = warp_n * 64 + nt * 8 + 2 * t;
                    float v0 = c[mt][nt][h * 2 + 0] + sbias[col];
                    float v1 = c[mt][nt][h * 2 + 1] + sbias[col + 1];
                    *(float2*)(Out + gr * (long)ldout + n0 + col) = make_float2(v0, v1);
                }
            }
        }
    }
}

// ---------------------------------------------------------------------------
// Fused FFN: Out = LN( resid + fc2(gelu(fc1(A))) ), one block per 128 rows.
// Hidden (128x512) processed in 4 chunks of 128 via SMEM, never leaves SM.
// ---------------------------------------------------------------------------
#define FFS   132
#define FFA   0
#define FFH   (16896 * 4)
#define FFW   (FFH + 16896 * 4)
#define FFBO  (FFW + 16896 * 4)
#define FFG   (FFBO + 512)
#define FFBB  (FFG + 512)
#define FFR1  (FFBB + 512)
#define FFR2  (FFR1 + 1024)
#define SMEM_FFN (FFR2 + 1024)

__global__ __launch_bounds__(256)
void k_ffn(const float* __restrict__ A, const float* __restrict__ F1T,
           const float* __restrict__ f1b, const float* __restrict__ F2T,
           const float* __restrict__ f2b, const float* __restrict__ resid,
           const float* __restrict__ lng, const float* __restrict__ lnb,
           float* __restrict__ Out) {
    extern __shared__ char smem[];
    uint32_t sbase = smem_u32(smem);
    float* SA  = (float*)(smem + FFA);
    float* SH  = (float*)(smem + FFH);
    float* SW  = (float*)(smem + FFW);
    float* sbo = (float*)(smem + FFBO);
    float* sg  = (float*)(smem + FFG);
    float* sbb = (float*)(smem + FFBB);
    float* sred1 = (float*)(smem + FFR1);
    float* sred2 = (float*)(smem + FFR2);
    const int tid = threadIdx.x;
    const int wid = tid >> 5, lane = tid & 31;
    const int g = lane >> 2, t4 = lane & 3;
    const int wm = wid & 3, wn = wid >> 2;
    const long m0 = (long)blockIdx.x * 128;

    if (tid < 128) { sbo[tid] = f2b[tid]; sg[tid] = lng[tid]; sbb[tid] = lnb[tid]; }

    // stage A (ffn_in rows, 128x128) once
#pragma unroll
    for (int i = 0; i < 16; i++) {
        int f = tid + i * 256;
        int r = f >> 5, c4 = (f & 31) * 4;
        cp16(sbase + FFA + (uint32_t)(r * FFS + c4) * 4, A + (m0 + r) * 128 + c4);
    }
    CP_COMMIT();

    float oacc[2][8][4];
#pragma unroll
    for (int mt = 0; mt < 2; mt++)
#pragma unroll
        for (int nt = 0; nt < 8; nt++)
#pragma unroll
            for (int j = 0; j < 4; j++) oacc[mt][nt][j] = 0.0f;

    for (int ch = 0; ch < 4; ch++) {
        // stage f1 chunk [128 hid rows x 128 k]
#pragma unroll
        for (int i = 0; i < 16; i++) {
            int f = tid + i * 256;
            int r = f >> 5, c4 = (f & 31) * 4;
            cp16(sbase + FFW + (uint32_t)(r * FFS + c4) * 4,
                 F1T + (long)(ch * 128 + r) * 128 + c4);
        }
        CP_COMMIT();
        CP_WAIT0();
        __syncthreads();

        // hidden = A @ f1_chunk^T
        float hacc[2][8][4];
#pragma unroll
        for (int mt = 0; mt < 2; mt++)
#pragma unroll
            for (int nt = 0; nt < 8; nt++)
#pragma unroll
                for (int j = 0; j < 4; j++) hacc[mt][nt][j] = 0.0f;
#pragma unroll
        for (int ks = 0; ks < 16; ks++) {
            int k0 = ks * 8 + t4;
            uint32_t a[2][4];
#pragma unroll
            for (int mt = 0; mt < 2; mt++) {
                const float* ap = SA + (wm * 32 + mt * 16 + g) * FFS + k0;
                a[mt][0] = f2tf(ap[0]);
                a[mt][1] = f2tf(ap[8 * FFS]);
                a[mt][2] = f2tf(ap[4]);
                a[mt][3] = f2tf(ap[8 * FFS + 4]);
            }
#pragma unroll
            for (int nt = 0; nt < 8; nt++) {
                const float* bp = SW + (wn * 64 + nt * 8 + g) * FFS + k0;
                uint32_t b0 = __float_as_uint(bp[0]);
                uint32_t b1 = __float_as_uint(bp[4]);
#pragma unroll
                for (int mt = 0; mt < 2; mt++) mma_tf32(hacc[mt][nt], a[mt], b0, b1);
            }
        }
        __syncthreads();  // all warps done reading SW(f1)

        // stage f2 chunk [128 out rows x 128 k-slice], ld 512
#pragma unroll
        for (int i = 0; i < 16; i++) {
            int f = tid + i * 256;
            int r = f >> 5, c4 = (f & 31) * 4;
            cp16(sbase + FFW + (uint32_t)(r * FFS + c4) * 4,
                 F2T + (long)r * 512 + ch * 128 + c4);
        }
        CP_COMMIT();

        // gelu(hidden + f1b) -> SH
#pragma unroll
        for (int mt = 0; mt < 2; mt++) {
#pragma unroll
            for (int h = 0; h < 2; h++) {
                int row = wm * 32 + mt * 16 + h * 8 + g;
#pragma unroll
                for (int nt = 0; nt < 8; nt++) {
                    int col = wn * 64 + nt * 8 + 2 * t4;
                    float b0 = f1b[ch * 128 + col];
                    float b1 = f1b[ch * 128 + col + 1];
                    SH[row * FFS + col]     = gelu_t(hacc[mt][nt][h * 2 + 0] + b0);
                    SH[row * FFS + col + 1] = gelu_t(hacc[mt][nt][h * 2 + 1] + b1);
                }
            }
        }
        CP_WAIT0();
        __syncthreads();

        // out += hidden @ f2_chunk^T
#pragma unroll
        for (int ks = 0; ks < 16; ks++) {
            int k0 = ks * 8 + t4;
            uint32_t a[2][4];
#pragma unroll
            for (int mt = 0; mt < 2; mt++) {
                const float* ap = SH + (wm * 32 + mt * 16 + g) * FFS + k0;
                a[mt][0] = f2tf(ap[0]);
                a[mt][1] = f2tf(ap[8 * FFS]);
                a[mt][2] = f2tf(ap[4]);
                a[mt][3] = f2tf(ap[8 * FFS + 4]);
            }
#pragma unroll
            for (int nt = 0; nt < 8; nt++) {
                const float* bp = SW + (wn * 64 + nt * 8 + g) * FFS + k0;
                uint32_t b0 = __float_as_uint(bp[0]);
                uint32_t b1 = __float_as_uint(bp[4]);
#pragma unroll
                for (int mt = 0; mt < 2; mt++) mma_tf32(oacc[mt][nt], a[mt], b0, b1);
            }
        }
        __syncthreads();  // before next chunk overwrites SH/SW
    }

    // epilogue: bias + residual + LN
#pragma unroll
    for (int mt = 0; mt < 2; mt++) {
#pragma unroll
        for (int h = 0; h < 2; h++) {
            int rib = wm * 32 + mt * 16 + h * 8 + g;
            long gr = m0 + rib;
            float s1 = 0.f, s2 = 0.f;
#pragma unroll
            for (int nt = 0; nt < 8; nt++) {
                int col = wn * 64 + nt * 8 + 2 * t4;
                float2 rv = *(const float2*)(resid + gr * 128 + col);
                float v0 = oacc[mt][nt][h * 2 + 0] + sbo[col]     + rv.x;
                float v1 = oacc[mt][nt][h * 2 + 1] + sbo[col + 1] + rv.y;
                oacc[mt][nt][h * 2 + 0] = v0;
                oacc[mt][nt][h * 2 + 1] = v1;
                s1 += v0 + v1;
                s2 += v0 * v0 + v1 * v1;
            }
            s1 += __shfl_xor_sync(0xffffffffu, s1, 1);
            s1 += __shfl_xor_sync(0xffffffffu, s1, 2);
            s2 += __shfl_xor_sync(0xffffffffu, s2, 1);
            s2 += __shfl_xor_sync(0xffffffffu, s2, 2);
            if (t4 == 0) {
                sred1[rib * 2 + wn] = s1;
                sred2[rib * 2 + wn] = s2;
            }
        }
    }
    __syncthreads();
#pragma unroll
    for (int mt = 0; mt < 2; mt++) {
#pragma unroll
        for (int h = 0; h < 2; h++) {
            int rib = wm * 32 + mt * 16 + h * 8 + g;
            long gr = m0 + rib;
            float s1 = sred1[rib * 2] + sred1[rib * 2 + 1];
            float s2 = sred2[rib * 2] + sred2[rib * 2 + 1];
            float mu = s1 * (1.0f / 128.0f);
            float var = s2 * (1.0f / 128.0f) - mu * mu;
            float rs = rsqrtf(var + 1e-5f);
#pragma unroll
            for (int nt = 0; nt < 8; nt++) {
                int col = wn * 64 + nt * 8 + 2 * t4;
                float o0 = (oacc[mt][nt][h * 2 + 0] - mu) * rs * sg[col]     + sbb[col];
                float o1 = (oacc[mt][nt][h * 2 + 1] - mu) * rs * sg[col + 1] + sbb[col + 1];
                *(float2*)(Out + gr * 128 + col) = make_float2(o0, o1);
            }
        }
    }
}

// ---------------------------------------------------------------------------
// x2 = LN(x1 + causal depthwise conv over time); one block per node, all T.
// ---------------------------------------------------------------------------
__global__ void k_conv_ln(const float* __restrict__ x1, const float* __restrict__ dk,
                          const float* __restrict__ g, const float* __restrict__ be,
                          float* __restrict__ out) {
    int n = blockIdx.x;
    int c = threadIdx.x;
    float xs[T_];
#pragma unroll
    for (int t = 0; t < T_; t++) xs[t] = x1[((long)t * N_ + n) * C_ + c];
    float w[K_];
#pragma unroll
    for (int j = 0; j < K_; j++) w[j] = dk[c * K_ + j];
    float gc = g[c], bc = be[c];
    __shared__ float red[8];
#pragma unroll
    for (int t = 0; t < T_; t++) {
        float v = xs[t];
#pragma unroll
        for (int j = 0; j < K_; j++)
            if (t - j >= 0) v += w[j] * xs[t - j];
        float s1 = warp_sum(v), s2 = warp_sum(v * v);
        int wi = c >> 5;
        if ((c & 31) == 0) { red[wi] = s1; red[4 + wi] = s2; }
        __syncthreads();
        float sum = red[0] + red[1] + red[2] + red[3];
        float sq  = red[4] + red[5] + red[6] + red[7];
        float mu = sum * (1.0f / 128.0f);
        float var = sq * (1.0f / 128.0f) - mu * mu;
        out[((long)t * N_ + n) * C_ + c] = (v - mu) * rsqrtf(var + 1e-5f) * gc + bc;
        __syncthreads();
    }
}

// ---------------------------------------------------------------------------
// Windowed attention: one block per node, 4 warps = 4 heads, all T in regs.
// ---------------------------------------------------------------------------
__global__ void k_attn(const float* __restrict__ q, const float* __restrict__ k,
                       const float* __restrict__ v, const int* __restrict__ tix,
                       float* __restrict__ out) {
    int n = blockIdx.x;
    int h = threadIdx.x >> 5, d = threadIdx.x & 31;
    long base0 = (long)n * C_ + h * DH_ + d;
    float qv[T_], kv[T_], vv[T_];
    int ti[T_];
#pragma unroll
    for (int t = 0; t < T_; t++) {
        long idx = base0 + (long)t * N_ * C_;
        qv[t] = q[idx]; kv[t] = k[idx]; vv[t] = v[idx];
        ti[t] = tix[t];
    }
#pragma unroll
    for (int t = 0; t < T_; t++) {
        float sc[WIN_];
#pragma unroll
        for (int w = 0; w < WIN_; w++) {
            int tp = t - w; if (tp < 0) tp = 0;
            bool ok = (t >= w) && ((ti[t] - ti[tp]) < WIN_);
            float pr = (t >= w) ? qv[t] * kv[tp] : 0.0f;
            float dot = warp_sum(pr) * 0.17677669529663687f;
            sc[w] = ok ? dot : -1e9f;
        }
        float mx = sc[0];
#pragma unroll
        for (int w = 1; w < WIN_; w++) mx = fmaxf(mx, sc[w]);
        float den = 0.0f, ex[WIN_];
#pragma unroll
        for (int w = 0; w < WIN_; w++) { ex[w] = expf(sc[w] - mx); den += ex[w]; }
        float o = 0.0f;
#pragma unroll
        for (int w = 0; w < WIN_; w++)
            if (t - w >= 0) o += ex[w] * vv[t - w];
        out[base0 + (long)t * N_ * C_] = o / den;
    }
}

// ---------------------------------------------------------------------------
// LIF scan over T + spike gate
// ---------------------------------------------------------------------------
__global__ void k_lif(const float* __restrict__ agg, float* __restrict__ spk_out,
                      float* __restrict__ ffn_in) {
    long i = (long)blockIdx.x * blockDim.x + threadIdx.x;
    if (i >= (long)N_ * C_) return;
    float vm = 0.0f;
#pragma unroll
    for (int t = 0; t < T_; t++) {
        long idx = (long)t * N_ * C_ + i;
        float a = agg[idx];
        float vn = 0.95f * vm + a;
        float s = (vn >= 1.0f) ? 1.0f : 0.0f;
        vm = vn * (1.0f - s);
        spk_out[idx] = s;
        ffn_in[idx]  = a * s;
    }
}

// ---------------------------------------------------------------------------
// spikes_hd.mean(-1) -> [T, N]
// ---------------------------------------------------------------------------
__global__ void k_spkmean(const float* __restrict__ spk, float* __restrict__ out) {
    long row = blockIdx.x;
    int c = threadIdx.x;
    float v = spk[row * C_ + c];
    __shared__ float red[4];
    float s = warp_sum(v);
    if ((c & 31) == 0) red[c >> 5] = s;
    __syncthreads();
    if (c == 0) out[row] = (red[0] + red[1] + red[2] + red[3]) * (1.0f / 128.0f);
}

// ---------------------------------------------------------------------------
// Launch
// ---------------------------------------------------------------------------
extern "C" void kernel_launch(void* const* d_in, const int* in_sizes, int n_in,
                              void* d_out, int out_size) {
    const float* x      = (const float*)d_in[0];
    const float* spikes = (const float*)d_in[1];
    const int*   ei     = (const int*)d_in[2];
    const int*   tix    = (const int*)d_in[3];
    const float* Ws  = (const float*)d_in[4];
    const float* bs  = (const float*)d_in[5];
    const float* dk  = (const float*)d_in[6];
    const float* g1  = (const float*)d_in[7];
    const float* b1  = (const float*)d_in[8];
    const float* g2  = (const float*)d_in[9];
    const float* b2  = (const float*)d_in[10];
    const float* gf  = (const float*)d_in[11];
    const float* bf  = (const float*)d_in[12];
    const float* Wq  = (const float*)d_in[13];
    const float* bq  = (const float*)d_in[14];
    const float* Wk  = (const float*)d_in[15];
    const float* bk  = (const float*)d_in[16];
    const float* Wv  = (const float*)d_in[17];
    const float* bv  = (const float*)d_in[18];
    const float* Wo  = (const float*)d_in[19];
    const float* bo  = (const float*)d_in[20];
    const float* f1w = (const float*)d_in[21];
    const float* f1b = (const float*)d_in[22];
    const float* f2w = (const float*)d_in[23];
    const float* f2b = (const float*)d_in[24];

    float *inv, *B1, *B2, *B3, *B4, *B5, *WT;
    int *cnt, *off, *cur, *srcs;
    cudaGetSymbolAddress((void**)&inv,  g_inv);
    cudaGetSymbolAddress((void**)&cnt,  g_cnt);
    cudaGetSymbolAddress((void**)&off,  g_off);
    cudaGetSymbolAddress((void**)&cur,  g_cur);
    cudaGetSymbolAddress((void**)&srcs, g_srcs);
    cudaGetSymbolAddress((void**)&B1,  g_B1);
    cudaGetSymbolAddress((void**)&B2,  g_B2);
    cudaGetSymbolAddress((void**)&B3,  g_B3);
    cudaGetSymbolAddress((void**)&B4,  g_B4);
    cudaGetSymbolAddress((void**)&B5,  g_B5);
    cudaGetSymbolAddress((void**)&WT,  g_WT);

    cudaFuncSetAttribute(k_gemm_mma<0>, cudaFuncAttributeMaxDynamicSharedMemorySize, SMEM_GEMM);
    cudaFuncSetAttribute(k_gemm_mma<2>, cudaFuncAttributeMaxDynamicSharedMemorySize, SMEM_GEMM);
    cudaFuncSetAttribute(k_ffn, cudaFuncAttributeMaxDynamicSharedMemorySize, SMEM_FFN);

    float* WsT = WT;
    float* WqT = WT + 16384;
    float* WkT = WT + 32768;
    float* WvT = WT + 49152;
    float* WoT = WT + 65536;
    float* f1T = WT + 81920;    // 512 x 128
    float* f2T = WT + 147456;   // 128 x 512

    const long tnc = (long)T_ * N_ * C_;
    const dim3 tb(32, 8);
    const int GW_BLOCKS = (TN_ * 32) / 256;  // 20000

    // CSR build
    cudaMemsetAsync(cnt, 0, N_ * sizeof(int));
    k_hist<<<(E_ + 255) / 256, 256>>>(ei, cnt);
    k_scan<<<1, 1024>>>(cnt, off, cur, inv);
    k_fill<<<(E_ + 255) / 256, 256>>>(ei, cur, srcs);

    // weight transposes + tf32 convert
    k_tcvt<<<dim3(4, 4),  tb>>>(Ws,  WsT, 128, 128);
    k_tcvt<<<dim3(4, 4),  tb>>>(Wq,  WqT, 128, 128);
    k_tcvt<<<dim3(4, 4),  tb>>>(Wk,  WkT, 128, 128);
    k_tcvt<<<dim3(4, 4),  tb>>>(Wv,  WvT, 128, 128);
    k_tcvt<<<dim3(4, 4),  tb>>>(Wo,  WoT, 128, 128);
    k_tcvt<<<dim3(16, 4), tb>>>(f1w, f1T, 128, 512);
    k_tcvt<<<dim3(4, 16), tb>>>(f2w, f2T, 512, 128);

    // spatial GNN: gather-mean -> GEMM(Ws) + residual(x) + LN1 -> x1=B3
    k_gather<false><<<GW_BLOCKS, 256>>>(x, off, srcs, spikes, inv, B1);
    k_gemm_mma<2><<<dim3(1, 1250), 256, SMEM_GEMM>>>(B1, WsT, bs, B3, 128, 128, x, g1, b1);

    // causal depthwise delay line + LN2 -> x2=B4
    k_conv_ln<<<N_, 128>>>(B3, dk, g2, b2, B4);

    // spike-gated message mean -> B1
    k_gather<true><<<GW_BLOCKS, 256>>>(B4, off, srcs, spikes, inv, B1);

    // q/k/v projections
    k_gemm_mma<0><<<dim3(1, 1250), 256, SMEM_GEMM>>>(B4, WqT, bq, B2, 128, 128, nullptr, nullptr, nullptr); // q=B2
    k_gemm_mma<0><<<dim3(1, 1250), 256, SMEM_GEMM>>>(B1, WkT, bk, B3, 128, 128, nullptr, nullptr, nullptr); // k=B3
    k_gemm_mma<0><<<dim3(1, 1250), 256, SMEM_GEMM>>>(B1, WvT, bv, B5, 128, 128, nullptr, nullptr, nullptr); // v=B5

    // windowed attention -> Wo projection
    k_attn<<<N_, 128>>>(B2, B3, B5, tix, B1);                                                               // attout=B1
    k_gemm_mma<0><<<dim3(1, 1250), 256, SMEM_GEMM>>>(B1, WoT, bo, B2, 128, 128, nullptr, nullptr, nullptr); // aggregated=B2

    // LIF scan + spike gate
    k_lif<<<(N_ * C_ + 255) / 256, 256>>>(B2, B3, B5);  // spikes_hd=B3, ffn_in=B5

    // fused FFN: gelu(fc1) -> fc2 + residual(x2) + LNf -> d_out
    k_ffn<<<1250, 256, SMEM_FFN>>>(B5, f1T, f1b, f2T, f2b, B4, gf, bf, (float*)d_out);

    // second output: spike mean over channels
    if (out_size >= (int)(tnc + (long)TN_))
        k_spkmean<<<TN_, 128>>>(B3, (float*)d_out + tnc);
}

// round 5
// speedup vs baseline: 2.8363x; 1.1350x over previous
#include <cuda_runtime.h>
#include <cuda_fp16.h>
#include <math.h>
#include <stdint.h>

// Problem constants
#define T_   8
#define N_   20000
#define C_   128
#define E_   320000
#define H_   4
#define DH_  32
#define WIN_ 4
#define K_   5
#define CH_  512
#define TN_  (T_ * N_)

// ---------------------------------------------------------------------------
// Scratch (__device__ globals; no cudaMalloc allowed)
// ---------------------------------------------------------------------------
__device__ float g_inv[N_];
__device__ int   g_cnt[N_];
__device__ int   g_off[N_ + 1];
__device__ int   g_cur[N_];
__device__ int   g_srcs[E_];
__device__ float g_B1[T_ * N_ * C_];
__device__ float g_B2[T_ * N_ * C_];
__device__ float g_B3[T_ * N_ * C_];
__device__ float g_B4[T_ * N_ * C_];
__device__ float g_B5[T_ * N_ * C_];
__device__ __half g_Xh[T_ * N_ * C_];   // fp16 copy of x (gather 1 input)
__device__ __half g_Gh[T_ * N_ * C_];   // fp16 pre-gated x2*spikes (gather 2 input)
// transposed+tf32-converted weights: Ws,Wq,Wk,Wv,Wo (128x128), f1 (512x128), f2 (128x512)
__device__ float g_WT[5 * 128 * 128 + 512 * 128 + 128 * 512];

// ---------------------------------------------------------------------------
// Helpers
// ---------------------------------------------------------------------------
__device__ __forceinline__ uint32_t smem_u32(const void* p) {
    uint32_t a;
    asm("{ .reg .u64 t; cvta.to.shared.u64 t, %1; cvt.u32.u64 %0, t; }" : "=r"(a) : "l"(p));
    return a;
}
__device__ __forceinline__ float warp_sum(float v) {
#pragma unroll
    for (int o = 16; o; o >>= 1) v += __shfl_xor_sync(0xffffffffu, v, o);
    return v;
}
__device__ __forceinline__ uint32_t f2tf(float v) {
    uint32_t u; asm("cvt.rna.tf32.f32 %0, %1;" : "=r"(u) : "f"(v)); return u;
}
__device__ __forceinline__ float gelu_t(float v) {
    float t = 0.7978845608028654f * (v + 0.044715f * v * v * v);
    float th; asm("tanh.approx.f32 %0, %1;" : "=f"(th) : "f"(t));
    return 0.5f * v * (1.0f + th);
}
__device__ __forceinline__ void cp16(uint32_t dst, const void* src) {
    asm volatile("cp.async.cg.shared.global [%0], [%1], 16;" :: "r"(dst), "l"(src));
}
#define CP_COMMIT() asm volatile("cp.async.commit_group;" ::: "memory")
#define CP_WAIT0()  asm volatile("cp.async.wait_group 0;" ::: "memory")
#define CP_WAIT1()  asm volatile("cp.async.wait_group 1;" ::: "memory")

__device__ __forceinline__ void mma_tf32(float* c, const uint32_t* a, uint32_t b0, uint32_t b1) {
    asm volatile("mma.sync.aligned.m16n8k8.row.col.f32.tf32.tf32.f32 "
                 "{%0,%1,%2,%3}, {%4,%5,%6,%7}, {%8,%9}, {%0,%1,%2,%3};"
                 : "+f"(c[0]), "+f"(c[1]), "+f"(c[2]), "+f"(c[3])
                 : "r"(a[0]), "r"(a[1]), "r"(a[2]), "r"(a[3]), "r"(b0), "r"(b1));
}

// ---------------------------------------------------------------------------
// fp32 -> fp16 convert (vectorized)
// ---------------------------------------------------------------------------
__global__ void k_f2h(const float* __restrict__ in, __half* __restrict__ out) {
    long i = ((long)blockIdx.x * blockDim.x + threadIdx.x) * 4;
    if (i >= (long)TN_ * C_) return;
    float4 v = *(const float4*)(in + i);
    __half2 h0 = __floats2half2_rn(v.x, v.y);
    __half2 h1 = __floats2half2_rn(v.z, v.w);
    uint2 u;
    u.x = *(uint32_t*)&h0;
    u.y = *(uint32_t*)&h1;
    *(uint2*)(out + i) = u;
}

// ---------------------------------------------------------------------------
// Weight transpose + tf32 convert: out[n*K+k] = tf32(in[k*N+n])
// ---------------------------------------------------------------------------
__device__ __forceinline__ void tcvt_body(const float* __restrict__ in,
                                          float* __restrict__ out, int Kd, int Ncol) {
    __shared__ float tile[32][33];
    int kb = blockIdx.y * 32, nb = blockIdx.x * 32;
    int tx = threadIdx.x, ty = threadIdx.y;
#pragma unroll
    for (int j = 0; j < 32; j += 8)
        tile[ty + j][tx] = in[(long)(kb + ty + j) * Ncol + nb + tx];
    __syncthreads();
#pragma unroll
    for (int j = 0; j < 32; j += 8) {
        float v = tile[tx][ty + j];
        out[(long)(nb + ty + j) * Kd + kb + tx] = __uint_as_float(f2tf(v));
    }
}

__global__ void k_tcvt(const float* __restrict__ in, float* __restrict__ out,
                       int Kd, int Ncol) {
    tcvt_body(in, out, Kd, Ncol);
}

// five 128x128 transposes in one launch (grid.z selects matrix)
__global__ void k_tcvt5(const float* w0, const float* w1, const float* w2,
                        const float* w3, const float* w4,
                        float* o0, float* o1, float* o2, float* o3, float* o4) {
    const float* in; float* out;
    switch (blockIdx.z) {
        case 0: in = w0; out = o0; break;
        case 1: in = w1; out = o1; break;
        case 2: in = w2; out = o2; break;
        case 3: in = w3; out = o3; break;
        default: in = w4; out = o4; break;
    }
    tcvt_body(in, out, 128, 128);
}

// ---------------------------------------------------------------------------
// CSR build: histogram -> scan -> fill
// ---------------------------------------------------------------------------
__global__ void k_hist(const int* __restrict__ ei, int* __restrict__ cnt) {
    int e = blockIdx.x * blockDim.x + threadIdx.x;
    if (e < E_) atomicAdd(&cnt[ei[E_ + e]], 1);
}

__global__ void k_scan(const int* __restrict__ cnt, int* __restrict__ off,
                       int* __restrict__ cur, float* __restrict__ inv) {
    __shared__ int wsum[32];
    __shared__ int sbase;
    __shared__ int stot;
    if (threadIdx.x == 0) sbase = 0;
    __syncthreads();
    int lane = threadIdx.x & 31, w = threadIdx.x >> 5;
    for (int start = 0; start < N_; start += 1024) {
        int i = start + threadIdx.x;
        int v = (i < N_) ? cnt[i] : 0;
        int s = v;
#pragma unroll
        for (int o = 1; o < 32; o <<= 1) {
            int tmp = __shfl_up_sync(0xffffffffu, s, o);
            if (lane >= o) s += tmp;
        }
        if (lane == 31) wsum[w] = s;
        __syncthreads();
        if (w == 0) {
            int ws = wsum[lane];
#pragma unroll
            for (int o = 1; o < 32; o <<= 1) {
                int tmp = __shfl_up_sync(0xffffffffu, ws, o);
                if (lane >= o) ws += tmp;
            }
            wsum[lane] = ws;
            if (lane == 31) stot = ws;
        }
        __syncthreads();
        int incl = s + (w > 0 ? wsum[w - 1] : 0) + sbase;
        if (i < N_) {
            int excl = incl - v;
            off[i] = excl;
            cur[i] = excl;
            inv[i] = 1.0f / fmaxf((float)v, 1.0f);
        }
        __syncthreads();
        if (threadIdx.x == 0) sbase += stot;
        __syncthreads();
    }
    if (threadIdx.x == 0) off[N_] = sbase;
}

__global__ void k_fill(const int* __restrict__ ei, int* __restrict__ cur,
                       int* __restrict__ srcs) {
    int e = blockIdx.x * blockDim.x + threadIdx.x;
    if (e >= E_) return;
    int d = ei[E_ + e];
    int idx = atomicAdd(&cur[d], 1);
    srcs[idx] = ei[e];
}

// ---------------------------------------------------------------------------
// fp16 gather-mean: out[t,n,:] = inv[n] * sum_{e: dst=n} xin_h[t,src,:]
// One warp per (t,n); lane handles 4 channels (8 bytes per edge).
// ---------------------------------------------------------------------------
__global__ void k_gather_h(const __half* __restrict__ xin, const int* __restrict__ off,
                           const int* __restrict__ srcs, const float* __restrict__ inv,
                           float* __restrict__ out) {
    int gw = (int)((blockIdx.x * blockDim.x + threadIdx.x) >> 5);
    int lane = threadIdx.x & 31;
    if (gw >= TN_) return;
    int t = gw / N_, n = gw - t * N_;
    int s0 = off[n], s1 = off[n + 1];
    const __half* xt = xin + (long)t * N_ * C_;
    float a0 = 0.f, a1 = 0.f, a2 = 0.f, a3 = 0.f;
    for (int j = s0; j < s1; j++) {
        int s = srcs[j];
        uint2 u = *(const uint2*)(xt + (long)s * C_ + lane * 4);
        __half2 h0 = *reinterpret_cast<__half2*>(&u.x);
        __half2 h1 = *reinterpret_cast<__half2*>(&u.y);
        float2 f0 = __half22float2(h0);
        float2 f1 = __half22float2(h1);
        a0 += f0.x; a1 += f0.y; a2 += f1.x; a3 += f1.y;
    }
    float iv = inv[n];
    *(float4*)(out + (long)gw * C_ + lane * 4) = make_float4(a0 * iv, a1 * iv, a2 * iv, a3 * iv);
}

// ---------------------------------------------------------------------------
// tf32 mma.sync GEMM: Out = epilogue( (A @ BT^T) + bias )
// EPI: 0 = bias (optional 2nd output for blockIdx.x==1), 2 = bias+resid+LN
// Block 128x128, BK=32, 256 threads (8 warps, 4(M)x2(N)), warp tile 32x64.
// ---------------------------------------------------------------------------
#define SA0   0
#define SA1   18432
#define SB0   36864
#define SB1   55296
#define SBIAS 73728
#define SG    74240
#define SBB   74752
#define SRED  75264
#define SMEM_GEMM (SRED + 2048)

template <int EPI>
__global__ __launch_bounds__(256)
void k_gemm_mma(const float* __restrict__ A, const float* __restrict__ BT,
                const float* __restrict__ bias, float* __restrict__ Out,
                int Kd,
                const float* __restrict__ bias2, float* __restrict__ Out2,
                const float* __restrict__ resid,
                const float* __restrict__ lng, const float* __restrict__ lnb) {
    extern __shared__ char smem[];
    uint32_t sbase = smem_u32(smem);
    const int tid = threadIdx.x;
    const int wid = tid >> 5, lane = tid & 31;
    const int g = lane >> 2, t = lane & 3;
    const int warp_m = wid & 3, warp_n = wid >> 2;
    const long m0 = (long)blockIdx.y * 128;
    const int  n0 = blockIdx.x * 128;

    const float* biasp = bias;
    float* outp = Out;
    if (EPI == 0 && blockIdx.x == 1) { biasp = bias2; outp = Out2; }

    float* sbias = (float*)(smem + SBIAS);
    float* sg    = (float*)(smem + SG);
    float* sbb   = (float*)(smem + SBB);
    float* sred1 = (float*)(smem + SRED);
    float* sred2 = (float*)(smem + SRED + 1024);

    if (tid < 128) {
        sbias[tid] = biasp[tid];
        if (EPI == 2) { sg[tid] = lng[tid]; sbb[tid] = lnb[tid]; }
    }

    float c[2][8][4];
#pragma unroll
    for (int mt = 0; mt < 2; mt++)
#pragma unroll
        for (int nt = 0; nt < 8; nt++)
#pragma unroll
            for (int j = 0; j < 4; j++) c[mt][nt][j] = 0.0f;

    const int lrow = tid >> 3;
    const int lcol = (tid & 7) * 4;
    const int nck = Kd >> 5;

    {
        uint32_t sa = sbase + SA0, sb = sbase + SB0;
#pragma unroll
        for (int i = 0; i < 4; i++) {
            int r = lrow + 32 * i;
            cp16(sa + (uint32_t)(r * 36 + lcol) * 4, A  + (m0 + r) * Kd + lcol);
            cp16(sb + (uint32_t)(r * 36 + lcol) * 4, BT + (long)(n0 + r) * Kd + lcol);
        }
        CP_COMMIT();
    }

    for (int ck = 0; ck < nck; ck++) {
        if (ck + 1 < nck) {
            int buf = (ck + 1) & 1;
            uint32_t sa = sbase + (buf ? SA1 : SA0);
            uint32_t sb = sbase + (buf ? SB1 : SB0);
            long kb = (long)(ck + 1) * 32;
#pragma unroll
            for (int i = 0; i < 4; i++) {
                int r = lrow + 32 * i;
                cp16(sa + (uint32_t)(r * 36 + lcol) * 4, A  + (m0 + r) * Kd + kb + lcol);
                cp16(sb + (uint32_t)(r * 36 + lcol) * 4, BT + (long)(n0 + r) * Kd + kb + lcol);
            }
            CP_COMMIT();
            CP_WAIT1();
        } else {
            CP_WAIT0();
        }
        __syncthreads();

        const float* As = (const float*)(smem + ((ck & 1) ? SA1 : SA0));
        const float* Bs = (const float*)(smem + ((ck & 1) ? SB1 : SB0));
#pragma unroll
        for (int ks = 0; ks < 4; ks++) {
            int k0 = ks * 8 + t;
            uint32_t a[2][4];
#pragma unroll
            for (int mt = 0; mt < 2; mt++) {
                const float* ap = As + (warp_m * 32 + mt * 16 + g) * 36 + k0;
                a[mt][0] = f2tf(ap[0]);
                a[mt][1] = f2tf(ap[8 * 36]);
                a[mt][2] = f2tf(ap[4]);
                a[mt][3] = f2tf(ap[8 * 36 + 4]);
            }
#pragma unroll
            for (int nt = 0; nt < 8; nt++) {
                const float* bp = Bs + (warp_n * 64 + nt * 8 + g) * 36 + k0;
                uint32_t b0 = __float_as_uint(bp[0]);
                uint32_t b1 = __float_as_uint(bp[4]);
#pragma unroll
                for (int mt = 0; mt < 2; mt++) mma_tf32(c[mt][nt], a[mt], b0, b1);
            }
        }
        __syncthreads();
    }

    if (EPI == 2) {
#pragma unroll
        for (int mt = 0; mt < 2; mt++) {
#pragma unroll
            for (int h = 0; h < 2; h++) {
                int rib = warp_m * 32 + mt * 16 + h * 8 + g;
                long gr = m0 + rib;
                float s1 = 0.f, s2 = 0.f;
#pragma unroll
                for (int nt = 0; nt < 8; nt++) {
                    int col = warp_n * 64 + nt * 8 + 2 * t;
                    float2 rv = *(const float2*)(resid + gr * 128 + col);
                    float v0 = c[mt][nt][h * 2 + 0] + sbias[col]     + rv.x;
                    float v1 = c[mt][nt][h * 2 + 1] + sbias[col + 1] + rv.y;
                    c[mt][nt][h * 2 + 0] = v0;
                    c[mt][nt][h * 2 + 1] = v1;
                    s1 += v0 + v1;
                    s2 += v0 * v0 + v1 * v1;
                }
                s1 += __shfl_xor_sync(0xffffffffu, s1, 1);
                s1 += __shfl_xor_sync(0xffffffffu, s1, 2);
                s2 += __shfl_xor_sync(0xffffffffu, s2, 1);
                s2 += __shfl_xor_sync(0xffffffffu, s2, 2);
                if (t == 0) {
                    sred1[rib * 2 + warp_n] = s1;
                    sred2[rib * 2 + warp_n] = s2;
                }
            }
        }
        __syncthreads();
#pragma unroll
        for (int mt = 0; mt < 2; mt++) {
#pragma unroll
            for (int h = 0; h < 2; h++) {
                int rib = warp_m * 32 + mt * 16 + h * 8 + g;
                long gr = m0 + rib;
                float s1 = sred1[rib * 2] + sred1[rib * 2 + 1];
                float s2 = sred2[rib * 2] + sred2[rib * 2 + 1];
                float mu = s1 * (1.0f / 128.0f);
                float var = s2 * (1.0f / 128.0f) - mu * mu;
                float rs = rsqrtf(var + 1e-5f);
#pragma unroll
                for (int nt = 0; nt < 8; nt++) {
                    int col = warp_n * 64 + nt * 8 + 2 * t;
                    float o0 = (c[mt][nt][h * 2 + 0] - mu) * rs * sg[col]     + sbb[col];
                    float o1 = (c[mt][nt][h * 2 + 1] - mu) * rs * sg[col + 1] + sbb[col + 1];
                    *(float2*)(Out + gr * 128 + col) = make_float2(o0, o1);
                }
            }
        }
    } else {
#pragma unroll
        for (int mt = 0; mt < 2; mt++) {
#pragma unroll
            for (int h = 0; h < 2; h++) {
                long gr = m0 + warp_m * 32 + mt * 16 + h * 8 + g;
#pragma unroll
                for (int nt = 0; nt < 8; nt++) {
                    int col = warp_n * 64 + nt * 8 + 2 * t;
                    float v0 = c[mt][nt][h * 2 + 0] + sbias[col];
                    float v1 = c[mt][nt][h * 2 + 1] + sbias[col + 1];
                    *(float2*)(outp + gr * 128 + col) = make_float2(v0, v1);
                }
            }
        }
    }
}

// ---------------------------------------------------------------------------
// Fused FFN: Out = LN( resid + fc2(gelu(fc1(A))) ), one block per 128 rows.
// ---------------------------------------------------------------------------
#define FFS   132
#define FFA   0
#define FFH   (16896 * 4)
#define FFW   (FFH + 16896 * 4)
#define FFBO  (FFW + 16896 * 4)
#define FFG   (FFBO + 512)
#define FFBB  (FFG + 512)
#define FFR1  (FFBB + 512)
#define FFR2  (FFR1 + 1024)
#define SMEM_FFN (FFR2 + 1024)

__global__ __launch_bounds__(256)
void k_ffn(const float* __restrict__ A, const float* __restrict__ F1T,
           const float* __restrict__ f1b, const float* __restrict__ F2T,
           const float* __restrict__ f2b, const float* __restrict__ resid,
           const float* __restrict__ lng, const float* __restrict__ lnb,
           float* __restrict__ Out) {
    extern __shared__ char smem[];
    uint32_t sbase = smem_u32(smem);
    float* SA  = (float*)(smem + FFA);
    float* SH  = (float*)(smem + FFH);
    float* SW  = (float*)(smem + FFW);
    float* sbo = (float*)(smem + FFBO);
    float* sg  = (float*)(smem + FFG);
    float* sbb = (float*)(smem + FFBB);
    float* sred1 = (float*)(smem + FFR1);
    float* sred2 = (float*)(smem + FFR2);
    const int tid = threadIdx.x;
    const int wid = tid >> 5, lane = tid & 31;
    const int g = lane >> 2, t4 = lane & 3;
    const int wm = wid & 3, wn = wid >> 2;
    const long m0 = (long)blockIdx.x * 128;

    if (tid < 128) { sbo[tid] = f2b[tid]; sg[tid] = lng[tid]; sbb[tid] = lnb[tid]; }

#pragma unroll
    for (int i = 0; i < 16; i++) {
        int f = tid + i * 256;
        int r = f >> 5, c4 = (f & 31) * 4;
        cp16(sbase + FFA + (uint32_t)(r * FFS + c4) * 4, A + (m0 + r) * 128 + c4);
    }
    CP_COMMIT();

    float oacc[2][8][4];
#pragma unroll
    for (int mt = 0; mt < 2; mt++)
#pragma unroll
        for (int nt = 0; nt < 8; nt++)
#pragma unroll
            for (int j = 0; j < 4; j++) oacc[mt][nt][j] = 0.0f;

    for (int ch = 0; ch < 4; ch++) {
#pragma unroll
        for (int i = 0; i < 16; i++) {
            int f = tid + i * 256;
            int r = f >> 5, c4 = (f & 31) * 4;
            cp16(sbase + FFW + (uint32_t)(r * FFS + c4) * 4,
                 F1T + (long)(ch * 128 + r) * 128 + c4);
        }
        CP_COMMIT();
        CP_WAIT0();
        __syncthreads();

        float hacc[2][8][4];
#pragma unroll
        for (int mt = 0; mt < 2; mt++)
#pragma unroll
            for (int nt = 0; nt < 8; nt++)
#pragma unroll
                for (int j = 0; j < 4; j++) hacc[mt][nt][j] = 0.0f;
#pragma unroll
        for (int ks = 0; ks < 16; ks++) {
            int k0 = ks * 8 + t4;
            uint32_t a[2][4];
#pragma unroll
            for (int mt = 0; mt < 2; mt++) {
                const float* ap = SA + (wm * 32 + mt * 16 + g) * FFS + k0;
                a[mt][0] = f2tf(ap[0]);
                a[mt][1] = f2tf(ap[8 * FFS]);
                a[mt][2] = f2tf(ap[4]);
                a[mt][3] = f2tf(ap[8 * FFS + 4]);
            }
#pragma unroll
            for (int nt = 0; nt < 8; nt++) {
                const float* bp = SW + (wn * 64 + nt * 8 + g) * FFS + k0;
                uint32_t b0 = __float_as_uint(bp[0]);
                uint32_t b1 = __float_as_uint(bp[4]);
#pragma unroll
                for (int mt = 0; mt < 2; mt++) mma_tf32(hacc[mt][nt], a[mt], b0, b1);
            }
        }
        __syncthreads();

#pragma unroll
        for (int i = 0; i < 16; i++) {
            int f = tid + i * 256;
            int r = f >> 5, c4 = (f & 31) * 4;
            cp16(sbase + FFW + (uint32_t)(r * FFS + c4) * 4,
                 F2T + (long)r * 512 + ch * 128 + c4);
        }
        CP_COMMIT();

#pragma unroll
        for (int mt = 0; mt < 2; mt++) {
#pragma unroll
            for (int h = 0; h < 2; h++) {
                int row = wm * 32 + mt * 16 + h * 8 + g;
#pragma unroll
                for (int nt = 0; nt < 8; nt++) {
                    int col = wn * 64 + nt * 8 + 2 * t4;
                    float b0 = f1b[ch * 128 + col];
                    float b1 = f1b[ch * 128 + col + 1];
                    SH[row * FFS + col]     = gelu_t(hacc[mt][nt][h * 2 + 0] + b0);
                    SH[row * FFS + col + 1] = gelu_t(hacc[mt][nt][h * 2 + 1] + b1);
                }
            }
        }
        CP_WAIT0();
        __syncthreads();

#pragma unroll
        for (int ks = 0; ks < 16; ks++) {
            int k0 = ks * 8 + t4;
            uint32_t a[2][4];
#pragma unroll
            for (int mt = 0; mt < 2; mt++) {
                const float* ap = SH + (wm * 32 + mt * 16 + g) * FFS + k0;
                a[mt][0] = f2tf(ap[0]);
                a[mt][1] = f2tf(ap[8 * FFS]);
                a[mt][2] = f2tf(ap[4]);
                a[mt][3] = f2tf(ap[8 * FFS + 4]);
            }
#pragma unroll
            for (int nt = 0; nt < 8; nt++) {
                const float* bp = SW + (wn * 64 + nt * 8 + g) * FFS + k0;
                uint32_t b0 = __float_as_uint(bp[0]);
                uint32_t b1 = __float_as_uint(bp[4]);
#pragma unroll
                for (int mt = 0; mt < 2; mt++) mma_tf32(oacc[mt][nt], a[mt], b0, b1);
            }
        }
        __syncthreads();
    }

#pragma unroll
    for (int mt = 0; mt < 2; mt++) {
#pragma unroll
        for (int h = 0; h < 2; h++) {
            int rib = wm * 32 + mt * 16 + h * 8 + g;
            long gr = m0 + rib;
            float s1 = 0.f, s2 = 0.f;
#pragma unroll
            for (int nt = 0; nt < 8; nt++) {
                int col = wn * 64 + nt * 8 + 2 * t4;
                float2 rv = *(const float2*)(resid + gr * 128 + col);
                float v0 = oacc[mt][nt][h * 2 + 0] + sbo[col]     + rv.x;
                float v1 = oacc[mt][nt][h * 2 + 1] + sbo[col + 1] + rv.y;
                oacc[mt][nt][h * 2 + 0] = v0;
                oacc[mt][nt][h * 2 + 1] = v1;
                s1 += v0 + v1;
                s2 += v0 * v0 + v1 * v1;
            }
            s1 += __shfl_xor_sync(0xffffffffu, s1, 1);
            s1 += __shfl_xor_sync(0xffffffffu, s1, 2);
            s2 += __shfl_xor_sync(0xffffffffu, s2, 1);
            s2 += __shfl_xor_sync(0xffffffffu, s2, 2);
            if (t4 == 0) {
                sred1[rib * 2 + wn] = s1;
                sred2[rib * 2 + wn] = s2;
            }
        }
    }
    __syncthreads();
#pragma unroll
    for (int mt = 0; mt < 2; mt++) {
#pragma unroll
        for (int h = 0; h < 2; h++) {
            int rib = wm * 32 + mt * 16 + h * 8 + g;
            long gr = m0 + rib;
            float s1 = sred1[rib * 2] + sred1[rib * 2 + 1];
            float s2 = sred2[rib * 2] + sred2[rib * 2 + 1];
            float mu = s1 * (1.0f / 128.0f);
            float var = s2 * (1.0f / 128.0f) - mu * mu;
            float rs = rsqrtf(var + 1e-5f);
#pragma unroll
            for (int nt = 0; nt < 8; nt++) {
                int col = wn * 64 + nt * 8 + 2 * t4;
                float o0 = (oacc[mt][nt][h * 2 + 0] - mu) * rs * sg[col]     + sbb[col];
                float o1 = (oacc[mt][nt][h * 2 + 1] - mu) * rs * sg[col + 1] + sbb[col + 1];
                *(float2*)(Out + gr * 128 + col) = make_float2(o0, o1);
            }
        }
    }
}

// ---------------------------------------------------------------------------
// x2 = LN(x1 + causal depthwise conv over time); one block per node, all T.
// Also emits fp16 pre-gated copy: gh = fp16(x2 * spikes) for the 2nd gather.
// ---------------------------------------------------------------------------
__global__ void k_conv_ln(const float* __restrict__ x1, const float* __restrict__ dk,
                          const float* __restrict__ g, const float* __restrict__ be,
                          const float* __restrict__ spikes,
                          float* __restrict__ out, __half* __restrict__ gh) {
    int n = blockIdx.x;
    int c = threadIdx.x;
    float xs[T_];
#pragma unroll
    for (int t = 0; t < T_; t++) xs[t] = x1[((long)t * N_ + n) * C_ + c];
    float w[K_];
#pragma unroll
    for (int j = 0; j < K_; j++) w[j] = dk[c * K_ + j];
    float gc = g[c], bc = be[c];
    __shared__ float red[8];
#pragma unroll
    for (int t = 0; t < T_; t++) {
        float v = xs[t];
#pragma unroll
        for (int j = 0; j < K_; j++)
            if (t - j >= 0) v += w[j] * xs[t - j];
        float s1 = warp_sum(v), s2 = warp_sum(v * v);
        int wi = c >> 5;
        if ((c & 31) == 0) { red[wi] = s1; red[4 + wi] = s2; }
        __syncthreads();
        float sum = red[0] + red[1] + red[2] + red[3];
        float sq  = red[4] + red[5] + red[6] + red[7];
        float mu = sum * (1.0f / 128.0f);
        float var = sq * (1.0f / 128.0f) - mu * mu;
        long idx = ((long)t * N_ + n) * C_ + c;
        float ov = (v - mu) * rsqrtf(var + 1e-5f) * gc + bc;
        out[idx] = ov;
        float spk = spikes[(long)t * N_ + n];
        gh[idx] = __float2half(ov * spk);
        __syncthreads();
    }
}

// ---------------------------------------------------------------------------
// Windowed attention: one block per node, 4 warps = 4 heads, all T in regs.
// ---------------------------------------------------------------------------
__global__ void k_attn(const float* __restrict__ q, const float* __restrict__ k,
                       const float* __restrict__ v, const int* __restrict__ tix,
                       float* __restrict__ out) {
    int n = blockIdx.x;
    int h = threadIdx.x >> 5, d = threadIdx.x & 31;
    long base0 = (long)n * C_ + h * DH_ + d;
    float qv[T_], kv[T_], vv[T_];
    int ti[T_];
#pragma unroll
    for (int t = 0; t < T_; t++) {
        long idx = base0 + (long)t * N_ * C_;
        qv[t] = q[idx]; kv[t] = k[idx]; vv[t] = v[idx];
        ti[t] = tix[t];
    }
#pragma unroll
    for (int t = 0; t < T_; t++) {
        float sc[WIN_];
#pragma unroll
        for (int w = 0; w < WIN_; w++) {
            int tp = t - w; if (tp < 0) tp = 0;
            bool ok = (t >= w) && ((ti[t] - ti[tp]) < WIN_);
            float pr = (t >= w) ? qv[t] * kv[tp] : 0.0f;
            float dot = warp_sum(pr) * 0.17677669529663687f;
            sc[w] = ok ? dot : -1e9f;
        }
        float mx = sc[0];
#pragma unroll
        for (int w = 1; w < WIN_; w++) mx = fmaxf(mx, sc[w]);
        float den = 0.0f, ex[WIN_];
#pragma unroll
        for (int w = 0; w < WIN_; w++) { ex[w] = expf(sc[w] - mx); den += ex[w]; }
        float o = 0.0f;
#pragma unroll
        for (int w = 0; w < WIN_; w++)
            if (t - w >= 0) o += ex[w] * vv[t - w];
        out[base0 + (long)t * N_ * C_] = o / den;
    }
}

// ---------------------------------------------------------------------------
// LIF scan + spike gate + channel-mean, one block (128 thr) per node.
// Writes ffn_in = agg*spike and spikes_hd.mean(-1) directly.
// ---------------------------------------------------------------------------
__global__ void k_lif2(const float* __restrict__ agg, float* __restrict__ ffn_in,
                       float* __restrict__ outm) {
    int n = blockIdx.x;
    int c = threadIdx.x;
    __shared__ float red[4];
    float vm = 0.0f;
#pragma unroll
    for (int t = 0; t < T_; t++) {
        long idx = ((long)t * N_ + n) * C_ + c;
        float a = agg[idx];
        float vn = 0.95f * vm + a;
        float s = (vn >= 1.0f) ? 1.0f : 0.0f;
        vm = vn * (1.0f - s);
        ffn_in[idx] = a * s;
        float ssum = warp_sum(s);
        if ((c & 31) == 0) red[c >> 5] = ssum;
        __syncthreads();
        if (c == 0) outm[(long)t * N_ + n] = (red[0] + red[1] + red[2] + red[3]) * (1.0f / 128.0f);
        __syncthreads();
    }
}

// ---------------------------------------------------------------------------
// Launch
// ---------------------------------------------------------------------------
extern "C" void kernel_launch(void* const* d_in, const int* in_sizes, int n_in,
                              void* d_out, int out_size) {
    const float* x      = (const float*)d_in[0];
    const float* spikes = (const float*)d_in[1];
    const int*   ei     = (const int*)d_in[2];
    const int*   tix    = (const int*)d_in[3];
    const float* Ws  = (const float*)d_in[4];
    const float* bs  = (const float*)d_in[5];
    const float* dk  = (const float*)d_in[6];
    const float* g1  = (const float*)d_in[7];
    const float* b1  = (const float*)d_in[8];
    const float* g2  = (const float*)d_in[9];
    const float* b2  = (const float*)d_in[10];
    const float* gf  = (const float*)d_in[11];
    const float* bf  = (const float*)d_in[12];
    const float* Wq  = (const float*)d_in[13];
    const float* bq  = (const float*)d_in[14];
    const float* Wk  = (const float*)d_in[15];
    const float* bk  = (const float*)d_in[16];
    const float* Wv  = (const float*)d_in[17];
    const float* bv  = (const float*)d_in[18];
    const float* Wo  = (const float*)d_in[19];
    const float* bo  = (const float*)d_in[20];
    const float* f1w = (const float*)d_in[21];
    const float* f1b = (const float*)d_in[22];
    const float* f2w = (const float*)d_in[23];
    const float* f2b = (const float*)d_in[24];

    float *inv, *B1, *B2, *B3, *B4, *B5, *WT;
    __half *Xh, *Gh;
    int *cnt, *off, *cur, *srcs;
    cudaGetSymbolAddress((void**)&inv,  g_inv);
    cudaGetSymbolAddress((void**)&cnt,  g_cnt);
    cudaGetSymbolAddress((void**)&off,  g_off);
    cudaGetSymbolAddress((void**)&cur,  g_cur);
    cudaGetSymbolAddress((void**)&srcs, g_srcs);
    cudaGetSymbolAddress((void**)&B1,  g_B1);
    cudaGetSymbolAddress((void**)&B2,  g_B2);
    cudaGetSymbolAddress((void**)&B3,  g_B3);
    cudaGetSymbolAddress((void**)&B4,  g_B4);
    cudaGetSymbolAddress((void**)&B5,  g_B5);
    cudaGetSymbolAddress((void**)&Xh,  g_Xh);
    cudaGetSymbolAddress((void**)&Gh,  g_Gh);
    cudaGetSymbolAddress((void**)&WT,  g_WT);

    cudaFuncSetAttribute(k_gemm_mma<0>, cudaFuncAttributeMaxDynamicSharedMemorySize, SMEM_GEMM);
    cudaFuncSetAttribute(k_gemm_mma<2>, cudaFuncAttributeMaxDynamicSharedMemorySize, SMEM_GEMM);
    cudaFuncSetAttribute(k_ffn, cudaFuncAttributeMaxDynamicSharedMemorySize, SMEM_FFN);

    float* WsT = WT;
    float* WqT = WT + 16384;
    float* WkT = WT + 32768;
    float* WvT = WT + 49152;   // contiguous after WkT (needed for fused KV GEMM)
    float* WoT = WT + 65536;
    float* f1T = WT + 81920;   // 512 x 128
    float* f2T = WT + 147456;  // 128 x 512

    const long tnc = (long)T_ * N_ * C_;
    const dim3 tb(32, 8);
    const int GW_BLOCKS = (TN_ * 32) / 256;  // 20000

    // CSR build
    cudaMemsetAsync(cnt, 0, N_ * sizeof(int));
    k_hist<<<(E_ + 255) / 256, 256>>>(ei, cnt);
    k_scan<<<1, 1024>>>(cnt, off, cur, inv);
    k_fill<<<(E_ + 255) / 256, 256>>>(ei, cur, srcs);

    // weight transposes + tf32 convert (five 128x128 in one launch)
    k_tcvt5<<<dim3(4, 4, 5), tb>>>(Ws, Wq, Wk, Wv, Wo, WsT, WqT, WkT, WvT, WoT);
    k_tcvt<<<dim3(16, 4), tb>>>(f1w, f1T, 128, 512);
    k_tcvt<<<dim3(4, 16), tb>>>(f2w, f2T, 512, 128);

    // fp16 copy of x for gather 1
    k_f2h<<<(int)(tnc / 4 / 256), 256>>>(x, Xh);

    // spatial GNN: gather-mean(fp16) -> GEMM(Ws) + residual(x) + LN1 -> x1=B3
    k_gather_h<<<GW_BLOCKS, 256>>>(Xh, off, srcs, inv, B1);
    k_gemm_mma<2><<<dim3(1, 1250), 256, SMEM_GEMM>>>(B1, WsT, bs, B3, 128,
                                                     nullptr, nullptr, x, g1, b1);

    // causal depthwise delay line + LN2 -> x2=B4, + fp16 pre-gated copy -> Gh
    k_conv_ln<<<N_, 128>>>(B3, dk, g2, b2, spikes, B4, Gh);

    // spike-gated message mean (fp16 gather of pre-gated x2) -> B1
    k_gather_h<<<GW_BLOCKS, 256>>>(Gh, off, srcs, inv, B1);

    // q projection; fused k+v projection (N=256, WkT|WvT contiguous)
    k_gemm_mma<0><<<dim3(1, 1250), 256, SMEM_GEMM>>>(B4, WqT, bq, B2, 128,
                                                     nullptr, nullptr, nullptr, nullptr, nullptr); // q=B2
    k_gemm_mma<0><<<dim3(2, 1250), 256, SMEM_GEMM>>>(B1, WkT, bk, B3, 128,
                                                     bv, B5, nullptr, nullptr, nullptr);           // k=B3, v=B5

    // windowed attention -> Wo projection
    k_attn<<<N_, 128>>>(B2, B3, B5, tix, B1);                                                      // attout=B1
    k_gemm_mma<0><<<dim3(1, 1250), 256, SMEM_GEMM>>>(B1, WoT, bo, B2, 128,
                                                     nullptr, nullptr, nullptr, nullptr, nullptr); // aggregated=B2

    // LIF scan + spike gate + channel mean (spike mean straight to d_out)
    float* outm = (out_size >= (int)(tnc + (long)TN_)) ? ((float*)d_out + tnc) : B3;
    k_lif2<<<N_, 128>>>(B2, B5, outm);  // ffn_in=B5

    // fused FFN: gelu(fc1) -> fc2 + residual(x2) + LNf -> d_out
    k_ffn<<<1250, 256, SMEM_FFN>>>(B5, f1T, f1b, f2T, f2b, B4, gf, bf, (float*)d_out);
}

// round 6
// speedup vs baseline: 3.6270x; 1.2787x over previous
#include <cuda_runtime.h>
#include <cuda_fp16.h>
#include <math.h>
#include <stdint.h>

// Problem constants
#define T_   8
#define N_   20000
#define C_   128
#define E_   320000
#define H_   4
#define DH_  32
#define WIN_ 4
#define K_   5
#define CH_  512
#define TN_  (T_ * N_)

// ---------------------------------------------------------------------------
// Scratch (__device__ globals; no cudaMalloc allowed)
// ---------------------------------------------------------------------------
__device__ float g_inv[N_];
__device__ int   g_cnt[N_];
__device__ int   g_off[N_ + 1];
__device__ int   g_cur[N_];
__device__ int   g_srcs[E_];
__device__ float g_B2[T_ * N_ * C_];   // aggregated (fp32, feeds LIF)
__device__ float g_B3[T_ * N_ * C_];   // x1 fp32
__device__ float g_B4[T_ * N_ * C_];   // x2 fp32 (resid for FFN)
__device__ __half g_Xh[T_ * N_ * C_];   // fp16 x (gather1 in); reused as attout
__device__ __half g_B1h[T_ * N_ * C_];  // fp16 gather outputs
__device__ __half g_X2h[T_ * N_ * C_];  // fp16 x2 (Q GEMM A)
__device__ __half g_Gh[T_ * N_ * C_];   // fp16 gated x2 (gather2 in)
__device__ __half g_Qh[T_ * N_ * C_];
__device__ __half g_Kh[T_ * N_ * C_];
__device__ __half g_Vh[T_ * N_ * C_];
__device__ __half g_Fh[T_ * N_ * C_];   // ffn_in fp16
// transposed fp16 weights: Ws,Wq,Wk,Wv,Wo (128x128), f1 (512x128), f2 (128x512)
__device__ __half g_WTh[5 * 128 * 128 + 512 * 128 + 128 * 512];

// ---------------------------------------------------------------------------
// Helpers
// ---------------------------------------------------------------------------
__device__ __forceinline__ uint32_t smem_u32(const void* p) {
    uint32_t a;
    asm("{ .reg .u64 t; cvta.to.shared.u64 t, %1; cvt.u32.u64 %0, t; }" : "=r"(a) : "l"(p));
    return a;
}
__device__ __forceinline__ float warp_sum(float v) {
#pragma unroll
    for (int o = 16; o; o >>= 1) v += __shfl_xor_sync(0xffffffffu, v, o);
    return v;
}
__device__ __forceinline__ float gelu_t(float v) {
    float t = 0.7978845608028654f * (v + 0.044715f * v * v * v);
    float th; asm("tanh.approx.f32 %0, %1;" : "=f"(th) : "f"(t));
    return 0.5f * v * (1.0f + th);
}
__device__ __forceinline__ void cp16(uint32_t dst, const void* src) {
    asm volatile("cp.async.cg.shared.global [%0], [%1], 16;" :: "r"(dst), "l"(src));
}
#define CP_COMMIT() asm volatile("cp.async.commit_group;" ::: "memory")
#define CP_WAIT0()  asm volatile("cp.async.wait_group 0;" ::: "memory")
#define CP_WAIT1()  asm volatile("cp.async.wait_group 1;" ::: "memory")

// fp16 MMA, fp32 accumulate: m16n8k16
__device__ __forceinline__ void mma_f16(float* c, const uint32_t* a, uint32_t b0, uint32_t b1) {
    asm volatile("mma.sync.aligned.m16n8k16.row.col.f32.f16.f16.f32 "
                 "{%0,%1,%2,%3}, {%4,%5,%6,%7}, {%8,%9}, {%0,%1,%2,%3};"
                 : "+f"(c[0]), "+f"(c[1]), "+f"(c[2]), "+f"(c[3])
                 : "r"(a[0]), "r"(a[1]), "r"(a[2]), "r"(a[3]), "r"(b0), "r"(b1));
}
__device__ __forceinline__ uint32_t ldu32(const __half* p) {
    return *(const uint32_t*)p;
}

// ---------------------------------------------------------------------------
// fp32 -> fp16 convert (vectorized)
// ---------------------------------------------------------------------------
__global__ void k_f2h(const float* __restrict__ in, __half* __restrict__ out) {
    long i = ((long)blockIdx.x * blockDim.x + threadIdx.x) * 4;
    if (i >= (long)TN_ * C_) return;
    float4 v = *(const float4*)(in + i);
    __half2 h0 = __floats2half2_rn(v.x, v.y);
    __half2 h1 = __floats2half2_rn(v.z, v.w);
    uint2 u;
    u.x = *(uint32_t*)&h0;
    u.y = *(uint32_t*)&h1;
    *(uint2*)(out + i) = u;
}

// ---------------------------------------------------------------------------
// Weight transpose + fp16 convert: out[n*K+k] = fp16(in[k*N+n])
// ---------------------------------------------------------------------------
__device__ __forceinline__ void tcvt_body(const float* __restrict__ in,
                                          __half* __restrict__ out, int Kd, int Ncol) {
    __shared__ float tile[32][33];
    int kb = blockIdx.y * 32, nb = blockIdx.x * 32;
    int tx = threadIdx.x, ty = threadIdx.y;
#pragma unroll
    for (int j = 0; j < 32; j += 8)
        tile[ty + j][tx] = in[(long)(kb + ty + j) * Ncol + nb + tx];
    __syncthreads();
#pragma unroll
    for (int j = 0; j < 32; j += 8) {
        float v = tile[tx][ty + j];
        out[(long)(nb + ty + j) * Kd + kb + tx] = __float2half(v);
    }
}

__global__ void k_tcvt(const float* __restrict__ in, __half* __restrict__ out,
                       int Kd, int Ncol) {
    tcvt_body(in, out, Kd, Ncol);
}

__global__ void k_tcvt5(const float* w0, const float* w1, const float* w2,
                        const float* w3, const float* w4,
                        __half* o0, __half* o1, __half* o2, __half* o3, __half* o4) {
    const float* in; __half* out;
    switch (blockIdx.z) {
        case 0: in = w0; out = o0; break;
        case 1: in = w1; out = o1; break;
        case 2: in = w2; out = o2; break;
        case 3: in = w3; out = o3; break;
        default: in = w4; out = o4; break;
    }
    tcvt_body(in, out, 128, 128);
}

// ---------------------------------------------------------------------------
// CSR build: histogram -> scan -> fill
// ---------------------------------------------------------------------------
__global__ void k_hist(const int* __restrict__ ei, int* __restrict__ cnt) {
    int e = blockIdx.x * blockDim.x + threadIdx.x;
    if (e < E_) atomicAdd(&cnt[ei[E_ + e]], 1);
}

__global__ void k_scan(const int* __restrict__ cnt, int* __restrict__ off,
                       int* __restrict__ cur, float* __restrict__ inv) {
    __shared__ int wsum[32];
    __shared__ int sbase;
    __shared__ int stot;
    if (threadIdx.x == 0) sbase = 0;
    __syncthreads();
    int lane = threadIdx.x & 31, w = threadIdx.x >> 5;
    for (int start = 0; start < N_; start += 1024) {
        int i = start + threadIdx.x;
        int v = (i < N_) ? cnt[i] : 0;
        int s = v;
#pragma unroll
        for (int o = 1; o < 32; o <<= 1) {
            int tmp = __shfl_up_sync(0xffffffffu, s, o);
            if (lane >= o) s += tmp;
        }
        if (lane == 31) wsum[w] = s;
        __syncthreads();
        if (w == 0) {
            int ws = wsum[lane];
#pragma unroll
            for (int o = 1; o < 32; o <<= 1) {
                int tmp = __shfl_up_sync(0xffffffffu, ws, o);
                if (lane >= o) ws += tmp;
            }
            wsum[lane] = ws;
            if (lane == 31) stot = ws;
        }
        __syncthreads();
        int incl = s + (w > 0 ? wsum[w - 1] : 0) + sbase;
        if (i < N_) {
            int excl = incl - v;
            off[i] = excl;
            cur[i] = excl;
            inv[i] = 1.0f / fmaxf((float)v, 1.0f);
        }
        __syncthreads();
        if (threadIdx.x == 0) sbase += stot;
        __syncthreads();
    }
    if (threadIdx.x == 0) off[N_] = sbase;
}

__global__ void k_fill(const int* __restrict__ ei, int* __restrict__ cur,
                       int* __restrict__ srcs) {
    int e = blockIdx.x * blockDim.x + threadIdx.x;
    if (e >= E_) return;
    int d = ei[E_ + e];
    int idx = atomicAdd(&cur[d], 1);
    srcs[idx] = ei[e];
}

// ---------------------------------------------------------------------------
// fp16 gather-mean -> fp16 out: one warp per (t,n); lane = 4 channels.
// ---------------------------------------------------------------------------
__global__ void k_gather_h(const __half* __restrict__ xin, const int* __restrict__ off,
                           const int* __restrict__ srcs, const float* __restrict__ inv,
                           __half* __restrict__ out) {
    int gw = (int)((blockIdx.x * blockDim.x + threadIdx.x) >> 5);
    int lane = threadIdx.x & 31;
    if (gw >= TN_) return;
    int t = gw / N_, n = gw - t * N_;
    int s0 = off[n], s1 = off[n + 1];
    const __half* xt = xin + (long)t * N_ * C_;
    float a0 = 0.f, a1 = 0.f, a2 = 0.f, a3 = 0.f;
    for (int j = s0; j < s1; j++) {
        int s = srcs[j];
        uint2 u = *(const uint2*)(xt + (long)s * C_ + lane * 4);
        float2 f0 = __half22float2(*reinterpret_cast<__half2*>(&u.x));
        float2 f1 = __half22float2(*reinterpret_cast<__half2*>(&u.y));
        a0 += f0.x; a1 += f0.y; a2 += f1.x; a3 += f1.y;
    }
    float iv = inv[n];
    __half2 h0 = __floats2half2_rn(a0 * iv, a1 * iv);
    __half2 h1 = __floats2half2_rn(a2 * iv, a3 * iv);
    uint2 u;
    u.x = *(uint32_t*)&h0;
    u.y = *(uint32_t*)&h1;
    *(uint2*)(out + (long)gw * C_ + lane * 4) = u;
}

// ---------------------------------------------------------------------------
// fp16 mma.sync GEMM: Out = epilogue( (A @ BT^T) + bias )
// EPI: 0 = bias (OUTH: half/float output; 2nd output for blockIdx.x==1)
//      2 = bias + residual + LayerNorm (float out)
// Block 128x128, BK=32, 256 threads (8 warps, 4(M)x2(N)), warp tile 32x64.
// fp16 SMEM chunk stride 40 halfs -> conflict-free 32-bit fragment loads.
// ---------------------------------------------------------------------------
#define LDA_  40
#define SA0   0
#define SA1   10240
#define SB0   20480
#define SB1   30720
#define SBIAS 40960
#define SG    41472
#define SBB   41984
#define SRED  42496
#define SMEM_GEMM (SRED + 2048)

template <int EPI, bool OUTH>
__global__ __launch_bounds__(256)
void k_gemm_mma(const __half* __restrict__ A, const __half* __restrict__ BT,
                const float* __restrict__ bias, void* __restrict__ OutV,
                int Kd,
                const float* __restrict__ bias2, void* __restrict__ Out2V,
                const float* __restrict__ resid,
                const float* __restrict__ lng, const float* __restrict__ lnb) {
    extern __shared__ char smem[];
    uint32_t sbase = smem_u32(smem);
    const int tid = threadIdx.x;
    const int wid = tid >> 5, lane = tid & 31;
    const int g = lane >> 2, t = lane & 3;
    const int warp_m = wid & 3, warp_n = wid >> 2;
    const long m0 = (long)blockIdx.y * 128;
    const int  n0 = blockIdx.x * 128;

    const float* biasp = bias;
    void* outv = OutV;
    if (EPI == 0 && blockIdx.x == 1) { biasp = bias2; outv = Out2V; }

    float* sbias = (float*)(smem + SBIAS);
    float* sg    = (float*)(smem + SG);
    float* sbb   = (float*)(smem + SBB);
    float* sred1 = (float*)(smem + SRED);
    float* sred2 = (float*)(smem + SRED + 1024);

    if (tid < 128) {
        sbias[tid] = biasp[tid];
        if (EPI == 2) { sg[tid] = lng[tid]; sbb[tid] = lnb[tid]; }
    }

    float c[2][8][4];
#pragma unroll
    for (int mt = 0; mt < 2; mt++)
#pragma unroll
        for (int nt = 0; nt < 8; nt++)
#pragma unroll
            for (int j = 0; j < 4; j++) c[mt][nt][j] = 0.0f;

    const int nck = Kd >> 5;
    // stage 0: 2 cp16 per thread per tensor (128 rows x 32 halfs)
    const int srow = tid >> 2;          // 0..63 base rows (x2 via i)
    const int sseg = (tid & 3) * 8;     // half offset within row (0,8,16,24)
    {
        uint32_t sa = sbase + SA0, sb = sbase + SB0;
#pragma unroll
        for (int i = 0; i < 2; i++) {
            int r = srow + 64 * i;
            cp16(sa + (uint32_t)(r * LDA_ + sseg) * 2, A  + (m0 + r) * Kd + sseg);
            cp16(sb + (uint32_t)(r * LDA_ + sseg) * 2, BT + (long)(n0 + r) * Kd + sseg);
        }
        CP_COMMIT();
    }

    for (int ck = 0; ck < nck; ck++) {
        if (ck + 1 < nck) {
            int buf = (ck + 1) & 1;
            uint32_t sa = sbase + (buf ? SA1 : SA0);
            uint32_t sb = sbase + (buf ? SB1 : SB0);
            long kb = (long)(ck + 1) * 32;
#pragma unroll
            for (int i = 0; i < 2; i++) {
                int r = srow + 64 * i;
                cp16(sa + (uint32_t)(r * LDA_ + sseg) * 2, A  + (m0 + r) * Kd + kb + sseg);
                cp16(sb + (uint32_t)(r * LDA_ + sseg) * 2, BT + (long)(n0 + r) * Kd + kb + sseg);
            }
            CP_COMMIT();
            CP_WAIT1();
        } else {
            CP_WAIT0();
        }
        __syncthreads();

        const __half* As = (const __half*)(smem + ((ck & 1) ? SA1 : SA0));
        const __half* Bs = (const __half*)(smem + ((ck & 1) ? SB1 : SB0));
#pragma unroll
        for (int ks = 0; ks < 2; ks++) {
            int k0 = ks * 16 + 2 * t;
            uint32_t a[2][4];
#pragma unroll
            for (int mt = 0; mt < 2; mt++) {
                const __half* ap = As + (warp_m * 32 + mt * 16 + g) * LDA_ + k0;
                a[mt][0] = ldu32(ap);
                a[mt][1] = ldu32(ap + 8 * LDA_);
                a[mt][2] = ldu32(ap + 8);
                a[mt][3] = ldu32(ap + 8 * LDA_ + 8);
            }
#pragma unroll
            for (int nt = 0; nt < 8; nt++) {
                const __half* bp = Bs + (warp_n * 64 + nt * 8 + g) * LDA_ + k0;
                uint32_t b0 = ldu32(bp);
                uint32_t b1 = ldu32(bp + 8);
#pragma unroll
                for (int mt = 0; mt < 2; mt++) mma_f16(c[mt][nt], a[mt], b0, b1);
            }
        }
        __syncthreads();
    }

    if (EPI == 2) {
        float* Out = (float*)OutV;
#pragma unroll
        for (int mt = 0; mt < 2; mt++) {
#pragma unroll
            for (int h = 0; h < 2; h++) {
                int rib = warp_m * 32 + mt * 16 + h * 8 + g;
                long gr = m0 + rib;
                float s1 = 0.f, s2 = 0.f;
#pragma unroll
                for (int nt = 0; nt < 8; nt++) {
                    int col = warp_n * 64 + nt * 8 + 2 * t;
                    float2 rv = *(const float2*)(resid + gr * 128 + col);
                    float v0 = c[mt][nt][h * 2 + 0] + sbias[col]     + rv.x;
                    float v1 = c[mt][nt][h * 2 + 1] + sbias[col + 1] + rv.y;
                    c[mt][nt][h * 2 + 0] = v0;
                    c[mt][nt][h * 2 + 1] = v1;
                    s1 += v0 + v1;
                    s2 += v0 * v0 + v1 * v1;
                }
                s1 += __shfl_xor_sync(0xffffffffu, s1, 1);
                s1 += __shfl_xor_sync(0xffffffffu, s1, 2);
                s2 += __shfl_xor_sync(0xffffffffu, s2, 1);
                s2 += __shfl_xor_sync(0xffffffffu, s2, 2);
                if (t == 0) {
                    sred1[rib * 2 + warp_n] = s1;
                    sred2[rib * 2 + warp_n] = s2;
                }
            }
        }
        __syncthreads();
#pragma unroll
        for (int mt = 0; mt < 2; mt++) {
#pragma unroll
            for (int h = 0; h < 2; h++) {
                int rib = warp_m * 32 + mt * 16 + h * 8 + g;
                long gr = m0 + rib;
                float s1 = sred1[rib * 2] + sred1[rib * 2 + 1];
                float s2 = sred2[rib * 2] + sred2[rib * 2 + 1];
                float mu = s1 * (1.0f / 128.0f);
                float var = s2 * (1.0f / 128.0f) - mu * mu;
                float rs = rsqrtf(var + 1e-5f);
#pragma unroll
                for (int nt = 0; nt < 8; nt++) {
                    int col = warp_n * 64 + nt * 8 + 2 * t;
                    float o0 = (c[mt][nt][h * 2 + 0] - mu) * rs * sg[col]     + sbb[col];
                    float o1 = (c[mt][nt][h * 2 + 1] - mu) * rs * sg[col + 1] + sbb[col + 1];
                    *(float2*)(Out + gr * 128 + col) = make_float2(o0, o1);
                }
            }
        }
    } else {
#pragma unroll
        for (int mt = 0; mt < 2; mt++) {
#pragma unroll
            for (int h = 0; h < 2; h++) {
                long gr = m0 + warp_m * 32 + mt * 16 + h * 8 + g;
#pragma unroll
                for (int nt = 0; nt < 8; nt++) {
                    int col = warp_n * 64 + nt * 8 + 2 * t;
                    float v0 = c[mt][nt][h * 2 + 0] + sbias[col];
                    float v1 = c[mt][nt][h * 2 + 1] + sbias[col + 1];
                    if (OUTH) {
                        __half2 hv = __floats2half2_rn(v0, v1);
                        *(__half2*)((__half*)outv + gr * 128 + col) = hv;
                    } else {
                        *(float2*)((float*)outv + gr * 128 + col) = make_float2(v0, v1);
                    }
                }
            }
        }
    }
}

// ---------------------------------------------------------------------------
// Fused FFN (fp16 operands): Out = LN( resid + fc2(gelu(fc1(A))) )
// One block per 128 rows; hidden never leaves the SM. FFS=136 halfs stride.
// ---------------------------------------------------------------------------
#define FFS   136
#define FFTB  (128 * FFS * 2)   // 34816 bytes per tile
#define FFA   0
#define FFH   FFTB
#define FFW   (2 * FFTB)
#define FFBO  (3 * FFTB)
#define FFG   (FFBO + 512)
#define FFBB  (FFG + 512)
#define FFR1  (FFBB + 512)
#define FFR2  (FFR1 + 1024)
#define SMEM_FFN (FFR2 + 1024)

__global__ __launch_bounds__(256)
void k_ffn(const __half* __restrict__ A, const __half* __restrict__ F1T,
           const float* __restrict__ f1b, const __half* __restrict__ F2T,
           const float* __restrict__ f2b, const float* __restrict__ resid,
           const float* __restrict__ lng, const float* __restrict__ lnb,
           float* __restrict__ Out) {
    extern __shared__ char smem[];
    uint32_t sbase = smem_u32(smem);
    __half* SA = (__half*)(smem + FFA);
    __half* SH = (__half*)(smem + FFH);
    __half* SW = (__half*)(smem + FFW);
    float* sbo = (float*)(smem + FFBO);
    float* sg  = (float*)(smem + FFG);
    float* sbb = (float*)(smem + FFBB);
    float* sred1 = (float*)(smem + FFR1);
    float* sred2 = (float*)(smem + FFR2);
    const int tid = threadIdx.x;
    const int wid = tid >> 5, lane = tid & 31;
    const int g = lane >> 2, t4 = lane & 3;
    const int wm = wid & 3, wn = wid >> 2;
    const long m0 = (long)blockIdx.x * 128;

    if (tid < 128) { sbo[tid] = f2b[tid]; sg[tid] = lng[tid]; sbb[tid] = lnb[tid]; }

    // stage A (128 rows x 128 halfs): 8 cp16/thread
    const int arow = tid >> 4;           // base row 0..15 (x8 via i)
    const int aseg = (tid & 15) * 8;     // half offset (0..120)
#pragma unroll
    for (int i = 0; i < 8; i++) {
        int r = arow + 16 * i;
        cp16(sbase + FFA + (uint32_t)(r * FFS + aseg) * 2, A + (m0 + r) * 128 + aseg);
    }
    CP_COMMIT();

    float oacc[2][8][4];
#pragma unroll
    for (int mt = 0; mt < 2; mt++)
#pragma unroll
        for (int nt = 0; nt < 8; nt++)
#pragma unroll
            for (int j = 0; j < 4; j++) oacc[mt][nt][j] = 0.0f;

    for (int ch = 0; ch < 4; ch++) {
#pragma unroll
        for (int i = 0; i < 8; i++) {
            int r = arow + 16 * i;
            cp16(sbase + FFW + (uint32_t)(r * FFS + aseg) * 2,
                 F1T + (long)(ch * 128 + r) * 128 + aseg);
        }
        CP_COMMIT();
        CP_WAIT0();
        __syncthreads();

        float hacc[2][8][4];
#pragma unroll
        for (int mt = 0; mt < 2; mt++)
#pragma unroll
            for (int nt = 0; nt < 8; nt++)
#pragma unroll
                for (int j = 0; j < 4; j++) hacc[mt][nt][j] = 0.0f;
#pragma unroll
        for (int ks = 0; ks < 8; ks++) {
            int k0 = ks * 16 + 2 * t4;
            uint32_t a[2][4];
#pragma unroll
            for (int mt = 0; mt < 2; mt++) {
                const __half* ap = SA + (wm * 32 + mt * 16 + g) * FFS + k0;
                a[mt][0] = ldu32(ap);
                a[mt][1] = ldu32(ap + 8 * FFS);
                a[mt][2] = ldu32(ap + 8);
                a[mt][3] = ldu32(ap + 8 * FFS + 8);
            }
#pragma unroll
            for (int nt = 0; nt < 8; nt++) {
                const __half* bp = SW + (wn * 64 + nt * 8 + g) * FFS + k0;
                uint32_t b0 = ldu32(bp);
                uint32_t b1 = ldu32(bp + 8);
#pragma unroll
                for (int mt = 0; mt < 2; mt++) mma_f16(hacc[mt][nt], a[mt], b0, b1);
            }
        }
        __syncthreads();

#pragma unroll
        for (int i = 0; i < 8; i++) {
            int r = arow + 16 * i;
            cp16(sbase + FFW + (uint32_t)(r * FFS + aseg) * 2,
                 F2T + (long)r * 512 + ch * 128 + aseg);
        }
        CP_COMMIT();

        // gelu(hidden + f1b) -> SH (fp16)
#pragma unroll
        for (int mt = 0; mt < 2; mt++) {
#pragma unroll
            for (int h = 0; h < 2; h++) {
                int row = wm * 32 + mt * 16 + h * 8 + g;
#pragma unroll
                for (int nt = 0; nt < 8; nt++) {
                    int col = wn * 64 + nt * 8 + 2 * t4;
                    float b0 = f1b[ch * 128 + col];
                    float b1 = f1b[ch * 128 + col + 1];
                    float h0 = gelu_t(hacc[mt][nt][h * 2 + 0] + b0);
                    float h1 = gelu_t(hacc[mt][nt][h * 2 + 1] + b1);
                    *(__half2*)(SH + row * FFS + col) = __floats2half2_rn(h0, h1);
                }
            }
        }
        CP_WAIT0();
        __syncthreads();

#pragma unroll
        for (int ks = 0; ks < 8; ks++) {
            int k0 = ks * 16 + 2 * t4;
            uint32_t a[2][4];
#pragma unroll
            for (int mt = 0; mt < 2; mt++) {
                const __half* ap = SH + (wm * 32 + mt * 16 + g) * FFS + k0;
                a[mt][0] = ldu32(ap);
                a[mt][1] = ldu32(ap + 8 * FFS);
                a[mt][2] = ldu32(ap + 8);
                a[mt][3] = ldu32(ap + 8 * FFS + 8);
            }
#pragma unroll
            for (int nt = 0; nt < 8; nt++) {
                const __half* bp = SW + (wn * 64 + nt * 8 + g) * FFS + k0;
                uint32_t b0 = ldu32(bp);
                uint32_t b1 = ldu32(bp + 8);
#pragma unroll
                for (int mt = 0; mt < 2; mt++) mma_f16(oacc[mt][nt], a[mt], b0, b1);
            }
        }
        __syncthreads();
    }

#pragma unroll
    for (int mt = 0; mt < 2; mt++) {
#pragma unroll
        for (int h = 0; h < 2; h++) {
            int rib = wm * 32 + mt * 16 + h * 8 + g;
            long gr = m0 + rib;
            float s1 = 0.f, s2 = 0.f;
#pragma unroll
            for (int nt = 0; nt < 8; nt++) {
                int col = wn * 64 + nt * 8 + 2 * t4;
                float2 rv = *(const float2*)(resid + gr * 128 + col);
                float v0 = oacc[mt][nt][h * 2 + 0] + sbo[col]     + rv.x;
                float v1 = oacc[mt][nt][h * 2 + 1] + sbo[col + 1] + rv.y;
                oacc[mt][nt][h * 2 + 0] = v0;
                oacc[mt][nt][h * 2 + 1] = v1;
                s1 += v0 + v1;
                s2 += v0 * v0 + v1 * v1;
            }
            s1 += __shfl_xor_sync(0xffffffffu, s1, 1);
            s1 += __shfl_xor_sync(0xffffffffu, s1, 2);
            s2 += __shfl_xor_sync(0xffffffffu, s2, 1);
            s2 += __shfl_xor_sync(0xffffffffu, s2, 2);
            if (t4 == 0) {
                sred1[rib * 2 + wn] = s1;
                sred2[rib * 2 + wn] = s2;
            }
        }
    }
    __syncthreads();
#pragma unroll
    for (int mt = 0; mt < 2; mt++) {
#pragma unroll
        for (int h = 0; h < 2; h++) {
            int rib = wm * 32 + mt * 16 + h * 8 + g;
            long gr = m0 + rib;
            float s1 = sred1[rib * 2] + sred1[rib * 2 + 1];
            float s2 = sred2[rib * 2] + sred2[rib * 2 + 1];
            float mu = s1 * (1.0f / 128.0f);
            float var = s2 * (1.0f / 128.0f) - mu * mu;
            float rs = rsqrtf(var + 1e-5f);
#pragma unroll
            for (int nt = 0; nt < 8; nt++) {
                int col = wn * 64 + nt * 8 + 2 * t4;
                float o0 = (oacc[mt][nt][h * 2 + 0] - mu) * rs * sg[col]     + sbb[col];
                float o1 = (oacc[mt][nt][h * 2 + 1] - mu) * rs * sg[col + 1] + sbb[col + 1];
                *(float2*)(Out + gr * 128 + col) = make_float2(o0, o1);
            }
        }
    }
}

// ---------------------------------------------------------------------------
// x2 = LN(x1 + causal depthwise conv over time); one block per node, all T.
// Emits x2 fp32 (resid), fp16 copy (Q GEMM A), fp16 pre-gated copy (gather 2).
// ---------------------------------------------------------------------------
__global__ void k_conv_ln(const float* __restrict__ x1, const float* __restrict__ dk,
                          const float* __restrict__ g, const float* __restrict__ be,
                          const float* __restrict__ spikes,
                          float* __restrict__ out, __half* __restrict__ outh,
                          __half* __restrict__ gh) {
    int n = blockIdx.x;
    int c = threadIdx.x;
    float xs[T_];
#pragma unroll
    for (int t = 0; t < T_; t++) xs[t] = x1[((long)t * N_ + n) * C_ + c];
    float w[K_];
#pragma unroll
    for (int j = 0; j < K_; j++) w[j] = dk[c * K_ + j];
    float gc = g[c], bc = be[c];
    __shared__ float red[8];
#pragma unroll
    for (int t = 0; t < T_; t++) {
        float v = xs[t];
#pragma unroll
        for (int j = 0; j < K_; j++)
            if (t - j >= 0) v += w[j] * xs[t - j];
        float s1 = warp_sum(v), s2 = warp_sum(v * v);
        int wi = c >> 5;
        if ((c & 31) == 0) { red[wi] = s1; red[4 + wi] = s2; }
        __syncthreads();
        float sum = red[0] + red[1] + red[2] + red[3];
        float sq  = red[4] + red[5] + red[6] + red[7];
        float mu = sum * (1.0f / 128.0f);
        float var = sq * (1.0f / 128.0f) - mu * mu;
        long idx = ((long)t * N_ + n) * C_ + c;
        float ov = (v - mu) * rsqrtf(var + 1e-5f) * gc + bc;
        out[idx] = ov;
        outh[idx] = __float2half(ov);
        float spk = spikes[(long)t * N_ + n];
        gh[idx] = __float2half(ov * spk);
        __syncthreads();
    }
}

// ---------------------------------------------------------------------------
// Windowed attention (fp16 I/O): one block per node, 4 warps = 4 heads.
// ---------------------------------------------------------------------------
__global__ void k_attn(const __half* __restrict__ q, const __half* __restrict__ k,
                       const __half* __restrict__ v, const int* __restrict__ tix,
                       __half* __restrict__ out) {
    int n = blockIdx.x;
    int h = threadIdx.x >> 5, d = threadIdx.x & 31;
    long base0 = (long)n * C_ + h * DH_ + d;
    float qv[T_], kv[T_], vv[T_];
    int ti[T_];
#pragma unroll
    for (int t = 0; t < T_; t++) {
        long idx = base0 + (long)t * N_ * C_;
        qv[t] = __half2float(q[idx]);
        kv[t] = __half2float(k[idx]);
        vv[t] = __half2float(v[idx]);
        ti[t] = tix[t];
    }
#pragma unroll
    for (int t = 0; t < T_; t++) {
        float sc[WIN_];
#pragma unroll
        for (int w = 0; w < WIN_; w++) {
            int tp = t - w; if (tp < 0) tp = 0;
            bool ok = (t >= w) && ((ti[t] - ti[tp]) < WIN_);
            float pr = (t >= w) ? qv[t] * kv[tp] : 0.0f;
            float dot = warp_sum(pr) * 0.17677669529663687f;
            sc[w] = ok ? dot : -1e9f;
        }
        float mx = sc[0];
#pragma unroll
        for (int w = 1; w < WIN_; w++) mx = fmaxf(mx, sc[w]);
        float den = 0.0f, ex[WIN_];
#pragma unroll
        for (int w = 0; w < WIN_; w++) { ex[w] = expf(sc[w] - mx); den += ex[w]; }
        float o = 0.0f;
#pragma unroll
        for (int w = 0; w < WIN_; w++)
            if (t - w >= 0) o += ex[w] * vv[t - w];
        out[base0 + (long)t * N_ * C_] = __float2half(o / den);
    }
}

// ---------------------------------------------------------------------------
// LIF scan + spike gate + channel-mean, one block (128 thr) per node.
// agg fp32 in; ffn_in fp16 out; spike channel-mean straight to output.
// ---------------------------------------------------------------------------
__global__ void k_lif2(const float* __restrict__ agg, __half* __restrict__ ffn_in,
                       float* __restrict__ outm) {
    int n = blockIdx.x;
    int c = threadIdx.x;
    __shared__ float red[4];
    float vm = 0.0f;
#pragma unroll
    for (int t = 0; t < T_; t++) {
        long idx = ((long)t * N_ + n) * C_ + c;
        float a = agg[idx];
        float vn = 0.95f * vm + a;
        float s = (vn >= 1.0f) ? 1.0f : 0.0f;
        vm = vn * (1.0f - s);
        ffn_in[idx] = __float2half(a * s);
        float ssum = warp_sum(s);
        if ((c & 31) == 0) red[c >> 5] = ssum;
        __syncthreads();
        if (c == 0) outm[(long)t * N_ + n] = (red[0] + red[1] + red[2] + red[3]) * (1.0f / 128.0f);
        __syncthreads();
    }
}

// ---------------------------------------------------------------------------
// Launch
// ---------------------------------------------------------------------------
extern "C" void kernel_launch(void* const* d_in, const int* in_sizes, int n_in,
                              void* d_out, int out_size) {
    const float* x      = (const float*)d_in[0];
    const float* spikes = (const float*)d_in[1];
    const int*   ei     = (const int*)d_in[2];
    const int*   tix    = (const int*)d_in[3];
    const float* Ws  = (const float*)d_in[4];
    const float* bs  = (const float*)d_in[5];
    const float* dk  = (const float*)d_in[6];
    const float* g1  = (const float*)d_in[7];
    const float* b1  = (const float*)d_in[8];
    const float* g2  = (const float*)d_in[9];
    const float* b2  = (const float*)d_in[10];
    const float* gf  = (const float*)d_in[11];
    const float* bf  = (const float*)d_in[12];
    const float* Wq  = (const float*)d_in[13];
    const float* bq  = (const float*)d_in[14];
    const float* Wk  = (const float*)d_in[15];
    const float* bk  = (const float*)d_in[16];
    const float* Wv  = (const float*)d_in[17];
    const float* bv  = (const float*)d_in[18];
    const float* Wo  = (const float*)d_in[19];
    const float* bo  = (const float*)d_in[20];
    const float* f1w = (const float*)d_in[21];
    const float* f1b = (const float*)d_in[22];
    const float* f2w = (const float*)d_in[23];
    const float* f2b = (const float*)d_in[24];

    float *inv, *B2, *B3, *B4;
    __half *Xh, *B1h, *X2h, *Gh, *Qh, *Kh, *Vh, *Fh, *WTh;
    int *cnt, *off, *cur, *srcs;
    cudaGetSymbolAddress((void**)&inv,  g_inv);
    cudaGetSymbolAddress((void**)&cnt,  g_cnt);
    cudaGetSymbolAddress((void**)&off,  g_off);
    cudaGetSymbolAddress((void**)&cur,  g_cur);
    cudaGetSymbolAddress((void**)&srcs, g_srcs);
    cudaGetSymbolAddress((void**)&B2,  g_B2);
    cudaGetSymbolAddress((void**)&B3,  g_B3);
    cudaGetSymbolAddress((void**)&B4,  g_B4);
    cudaGetSymbolAddress((void**)&Xh,  g_Xh);
    cudaGetSymbolAddress((void**)&B1h, g_B1h);
    cudaGetSymbolAddress((void**)&X2h, g_X2h);
    cudaGetSymbolAddress((void**)&Gh,  g_Gh);
    cudaGetSymbolAddress((void**)&Qh,  g_Qh);
    cudaGetSymbolAddress((void**)&Kh,  g_Kh);
    cudaGetSymbolAddress((void**)&Vh,  g_Vh);
    cudaGetSymbolAddress((void**)&Fh,  g_Fh);
    cudaGetSymbolAddress((void**)&WTh, g_WTh);

    cudaFuncSetAttribute((const void*)k_gemm_mma<0, true>,  cudaFuncAttributeMaxDynamicSharedMemorySize, SMEM_GEMM);
    cudaFuncSetAttribute((const void*)k_gemm_mma<0, false>, cudaFuncAttributeMaxDynamicSharedMemorySize, SMEM_GEMM);
    cudaFuncSetAttribute((const void*)k_gemm_mma<2, false>, cudaFuncAttributeMaxDynamicSharedMemorySize, SMEM_GEMM);
    cudaFuncSetAttribute((const void*)k_ffn, cudaFuncAttributeMaxDynamicSharedMemorySize, SMEM_FFN);

    __half* WsT = WTh;
    __half* WqT = WTh + 16384;
    __half* WkT = WTh + 32768;
    __half* WvT = WTh + 49152;   // contiguous after WkT (fused KV GEMM)
    __half* WoT = WTh + 65536;
    __half* f1T = WTh + 81920;   // 512 x 128
    __half* f2T = WTh + 147456;  // 128 x 512

    const long tnc = (long)T_ * N_ * C_;
    const dim3 tb(32, 8);
    const int GW_BLOCKS = (TN_ * 32) / 256;  // 20000

    // CSR build
    cudaMemsetAsync(cnt, 0, N_ * sizeof(int));
    k_hist<<<(E_ + 255) / 256, 256>>>(ei, cnt);
    k_scan<<<1, 1024>>>(cnt, off, cur, inv);
    k_fill<<<(E_ + 255) / 256, 256>>>(ei, cur, srcs);

    // weight transposes + fp16 convert
    k_tcvt5<<<dim3(4, 4, 5), tb>>>(Ws, Wq, Wk, Wv, Wo, WsT, WqT, WkT, WvT, WoT);
    k_tcvt<<<dim3(16, 4), tb>>>(f1w, f1T, 128, 512);
    k_tcvt<<<dim3(4, 16), tb>>>(f2w, f2T, 512, 128);

    // fp16 copy of x for gather 1
    k_f2h<<<(int)(tnc / 4 / 256), 256>>>(x, Xh);

    // spatial GNN: gather-mean(fp16) -> GEMM(Ws) + residual(x) + LN1 -> x1=B3
    k_gather_h<<<GW_BLOCKS, 256>>>(Xh, off, srcs, inv, B1h);
    k_gemm_mma<2, false><<<dim3(1, 1250), 256, SMEM_GEMM>>>(B1h, WsT, bs, B3, 128,
                                                            nullptr, nullptr, x, g1, b1);

    // causal depthwise delay line + LN2 -> x2=B4 (+fp16 copies)
    k_conv_ln<<<N_, 128>>>(B3, dk, g2, b2, spikes, B4, X2h, Gh);

    // spike-gated message mean (fp16 gather of pre-gated x2) -> B1h
    k_gather_h<<<GW_BLOCKS, 256>>>(Gh, off, srcs, inv, B1h);

    // q projection; fused k+v projection (grid.x=2, WkT|WvT contiguous)
    k_gemm_mma<0, true><<<dim3(1, 1250), 256, SMEM_GEMM>>>(X2h, WqT, bq, Qh, 128,
                                                           nullptr, nullptr, nullptr, nullptr, nullptr);
    k_gemm_mma<0, true><<<dim3(2, 1250), 256, SMEM_GEMM>>>(B1h, WkT, bk, Kh, 128,
                                                           bv, Vh, nullptr, nullptr, nullptr);

    // windowed attention (fp16 I/O; attout reuses Xh) -> Wo projection (fp32 out)
    k_attn<<<N_, 128>>>(Qh, Kh, Vh, tix, Xh);
    k_gemm_mma<0, false><<<dim3(1, 1250), 256, SMEM_GEMM>>>(Xh, WoT, bo, B2, 128,
                                                            nullptr, nullptr, nullptr, nullptr, nullptr);

    // LIF scan + spike gate + channel mean (spike mean straight to d_out)
    float* outm = (out_size >= (int)(tnc + (long)TN_)) ? ((float*)d_out + tnc) : B3;
    k_lif2<<<N_, 128>>>(B2, Fh, outm);

    // fused FFN (fp16): gelu(fc1) -> fc2 + residual(x2) + LNf -> d_out
    k_ffn<<<1250, 256, SMEM_FFN>>>(Fh, f1T, f1b, f2T, f2b, B4, gf, bf, (float*)d_out);
}